// round 9
// baseline (speedup 1.0000x reference)
#include <cuda_runtime.h>
#include <cstdint>

typedef unsigned long long ULL;
typedef unsigned char u8;
typedef unsigned int u32;

// ---------------- problem dims ----------------
#define T_  4
#define B_  8
#define S_  1024
#define D_  768
#define HF_ 3072
#define SD_   (S_*D_)
#define SH_   (S_*HF_)
#define BSD_  (B_*SD_)
#define BSH_  (B_*SH_)
#define TBSD_ (T_*BSD_)
#define TBSH_ (T_*BSH_)
#define TBD_  (T_*B_*D_)
#define BD_   (B_*D_)
#define MROWS_ (T_*B_*S_)

#define KC_  256   // Eigen gebp k-panel (confirmed R4)
#define KS_  32    // k per GEMM pipeline stage (1 mask word)

// bn-stat stages
#define ST_Q   0
#define ST_V   1
#define ST_K   2
#define ST_ATT 3
#define ST_O1  4
#define ST_O2  5

// ---------------- device scratch ----------------
__device__ u8    g_sp  [TBSD_];
__device__ float g_q   [TBSD_];
__device__ float g_k   [TBSD_];
__device__ float g_v   [TBSD_];
__device__ u8    g_qs  [TBSD_];
__device__ u8    g_ks  [TBSD_];
__device__ u8    g_vs  [TBSD_];
__device__ u8    g_qkvm[TBSD_];
__device__ float g_att [TBSD_];
__device__ float g_h   [TBSD_];
__device__ u8    g_sp2 [TBSD_];
__device__ float g_o1  [TBSH_];
__device__ u8    g_s1  [TBSH_];
__device__ float g_o2  [TBSD_];
__device__ int   g_qkp [4*TBD_];
__device__ u8    g_qks [TBD_];
__device__ float g_part[8*512];
__device__ float g_mean [6*8];
__device__ float g_denom[6*8];

// bitmasks, TRANSPOSED: [k/32][M] (contiguous in M for cp.async)
__device__ u32 g_msk_sp  [(D_/32)*MROWS_];
__device__ u32 g_msk_qkvm[(D_/32)*MROWS_];
__device__ u32 g_msk_sp2 [(D_/32)*MROWS_];
__device__ u32 g_msk_s1  [(HF_/32)*MROWS_];

// pointer tables (capture-safe: host never queries symbols)
__device__ u8*    g_ptrB[4];
__device__ u32*   g_ptrM[4];
__device__ float* g_ptrF[6];
__global__ void k_init_ptrs() {
    if (threadIdx.x == 0 && blockIdx.x == 0) {
        g_ptrB[0] = g_sp;     g_ptrB[1] = g_qkvm;   g_ptrB[2] = g_sp2;   g_ptrB[3] = g_s1;
        g_ptrM[0] = g_msk_sp; g_ptrM[1] = g_msk_qkvm; g_ptrM[2] = g_msk_sp2; g_ptrM[3] = g_msk_s1;
        g_ptrF[0] = g_q;   g_ptrF[1] = g_k;    g_ptrF[2] = g_v;
        g_ptrF[3] = g_att; g_ptrF[4] = g_o1;   g_ptrF[5] = g_o2;
    }
}

// ---------------- f32x2 helpers (bitwise 2x IEEE fp32 ops) ----------------
__device__ __forceinline__ ULL add2(ULL a, ULL b) {
    ULL r; asm("add.rn.f32x2 %0, %1, %2;" : "=l"(r) : "l"(a), "l"(b)); return r;
}
__device__ __forceinline__ float2 unpack2(ULL v) {
    float2 r; asm("mov.b64 {%0, %1}, %2;" : "=f"(r.x), "=f"(r.y) : "l"(v)); return r;
}

// ---------------- cp.async helpers ----------------
__device__ __forceinline__ void cp_async16(uint32_t smem, const void* g) {
    asm volatile("cp.async.cg.shared.global [%0], [%1], 16;" :: "r"(smem), "l"(g));
}
__device__ __forceinline__ void cp_commit() {
    asm volatile("cp.async.commit_group;");
}
__device__ __forceinline__ void cp_wait1() {
    asm volatile("cp.async.wait_group 1;");
}
__device__ __forceinline__ void cp_wait0() {
    asm volatile("cp.async.wait_group 0;");
}

// ---------------- sparse spike GEMM (sgemm6) ----------------
// C[M,N] = spikes(A) @ B[K,N] (+bias), A given as bitmasks MaskT[k/32][M].
// BITWISE identical to the Eigen-emulating dense chain: per output, ascending-k
// FADD of B[k][n] for set bits only (skipped fma(0,..) are exact identities;
// dummy +0.0 adds from the zero row are exact identities), panels of 256 k
// combined by FADD in ascending order, bias last.
// Tile 128x128, 512 threads: warp = 8 rows, lane = 4 cols.
__global__ __launch_bounds__(512)
void sgemm6(int aSel, const float* __restrict__ Bm, const float* __restrict__ bias,
            int cSel, int N, int K)
{
    __shared__ __align__(16) float Bs[2][33][128];  // row 32 = zeros (dummy)
    __shared__ __align__(16) u32  Msm[2][128];

    const u32* __restrict__ Mt = g_ptrM[aSel];
    float* __restrict__ C = g_ptrF[cSel];

    const int tid  = threadIdx.x;
    const int wid  = tid >> 5;          // 0..15
    const int lane = tid & 31;
    const int bn = blockIdx.x, bm = blockIdx.y;
    const int lane4 = lane * 4;

    // copy mapping: 32 rows x 128 cols per stage
    const int crow = tid >> 4;          // 0..31
    const int cch  = (tid & 15) * 8;    // float offset, 0..120 step 8 (32B)

    uint32_t sB0 = (uint32_t)__cvta_generic_to_shared(&Bs[0][crow][cch]);
    uint32_t sB1 = (uint32_t)__cvta_generic_to_shared(&Bs[1][crow][cch]);
    uint32_t sM0 = (uint32_t)__cvta_generic_to_shared(&Msm[0][0]);
    uint32_t sM1 = (uint32_t)__cvta_generic_to_shared(&Msm[1][0]);

    // zero dummy rows (row 32) of both stages
    if (tid < 128) { Bs[0][32][tid] = 0.0f; Bs[1][32][tid] = 0.0f; }

    const int S = K / KS_;

    // prologue: copy stage 0
    {
        const float* src = Bm + (size_t)crow * N + bn * 128 + cch;
        cp_async16(sB0, src);
        cp_async16(sB0 + 16, src + 4);
        if (tid < 32)
            cp_async16(sM0 + tid * 16, Mt + (size_t)0 * MROWS_ + bm * 128 + tid * 4);
        cp_commit();
    }

    ULL acc[8][2], part[8][2];
#pragma unroll
    for (int r = 0; r < 8; r++) {
        acc[r][0] = 0ULL; acc[r][1] = 0ULL;
        part[r][0] = 0ULL; part[r][1] = 0ULL;
    }

    for (int s = 0; s < S; s++) {
        const int buf = s & 1;
        if (s + 1 < S) {
            const int k0 = (s + 1) * KS_;
            const float* src = Bm + (size_t)(k0 + crow) * N + bn * 128 + cch;
            uint32_t dB = buf ? sB0 : sB1;
            cp_async16(dB, src);
            cp_async16(dB + 16, src + 4);
            if (tid < 32)
                cp_async16((buf ? sM0 : sM1) + tid * 16,
                           Mt + (size_t)(s + 1) * MROWS_ + bm * 128 + tid * 4);
            cp_commit();
            cp_wait1();
        } else {
            cp_wait0();
        }
        __syncthreads();

#pragma unroll
        for (int r = 0; r < 8; r++) {
            u32 w = Msm[buf][wid * 8 + r];
            int n4 = (__popc(w) + 3) >> 2;
            ULL p0 = part[r][0], p1 = part[r][1];
            for (int it = 0; it < n4; it++) {
#pragma unroll
                for (int u = 0; u < 4; u++) {
                    int k = w ? (__ffs(w) - 1) : 32;   // 32 -> zero row (+0.0)
                    w &= (w - 1);
                    const ULL* bp = (const ULL*)&Bs[buf][k][lane4];
                    p0 = add2(p0, bp[0]);
                    p1 = add2(p1, bp[1]);
                }
            }
            part[r][0] = p0; part[r][1] = p1;
        }
        __syncthreads();   // protect buf from next iteration's copy

        // Eigen panel boundary (every 256 k): FADD-flush part into acc
        if (((s + 1) & 7) == 0) {
#pragma unroll
            for (int r = 0; r < 8; r++) {
                acc[r][0] = add2(acc[r][0], part[r][0]); part[r][0] = 0ULL;
                acc[r][1] = add2(acc[r][1], part[r][1]); part[r][1] = 0ULL;
            }
        }
    }

    float bb[4];
#pragma unroll
    for (int j = 0; j < 4; j++)
        bb[j] = bias ? bias[bn * 128 + lane4 + j] : 0.0f;

#pragma unroll
    for (int r = 0; r < 8; r++) {
        int row = bm * 128 + wid * 8 + r;
        float2 q0 = unpack2(acc[r][0]), q1 = unpack2(acc[r][1]);
        *(float4*)(C + (size_t)row * N + bn * 128 + lane4) =
            make_float4(q0.x + bb[0], q0.y + bb[1], q1.x + bb[2], q1.y + bb[3]);
    }
}

// ---------------- pack u8 spikes [M][K] -> bitmask [K/32][M] ----------------
__global__ void k_pack(int sel, int KW) {
    const u8* __restrict__ X = g_ptrB[sel];
    u32* __restrict__ Y = g_ptrM[sel];
    int kw = blockIdx.x;
    int m = blockIdx.y * 8 + (threadIdx.x >> 5);
    int lane = threadIdx.x & 31;
    u8 v = X[(size_t)m * (KW * 32) + kw * 32 + lane];
    u32 bal = __ballot_sync(0xffffffffu, v != 0);
    if (lane == 0) Y[(size_t)kw * MROWS_ + m] = bal;
}

// ---------------- IF on input x -> sp bytes ----------------
__global__ void k_ifx(const float* __restrict__ x) {
    int j = blockIdx.x * blockDim.x + threadIdx.x;
    if (j >= BSD_) return;
    float vm = 0.0f;
#pragma unroll
    for (int t = 0; t < T_; t++) {
        int idx = t * BSD_ + j;
        vm += x[idx];
        float s = (vm >= 1.0f) ? 1.0f : 0.0f;
        g_sp[idx] = (u8)s;
        vm *= (1.0f - s);
    }
}

// ---------------- BN pass A: per-batch sum -> mean ----------------
__global__ void k_redA(int sel, int SDv) {
    const float* __restrict__ X = g_ptrF[sel];
    int b = blockIdx.y;
    int E = T_ * SDv;
    float s = 0.0f;
    for (int i = blockIdx.x * 256 + threadIdx.x; i < E; i += 512 * 256) {
        int t = i / SDv;
        int r = i - t * SDv;
        s += X[(size_t)(t * B_ + b) * SDv + r];
    }
    __shared__ float sh[256];
    int tid = threadIdx.x;
    sh[tid] = s; __syncthreads();
    for (int o = 128; o > 0; o >>= 1) { if (tid < o) sh[tid] += sh[tid + o]; __syncthreads(); }
    if (tid == 0) g_part[b * 512 + blockIdx.x] = sh[0];
}

__global__ void k_finA(int SDv, int stage) {
    int b = blockIdx.x, tid = threadIdx.x;
    double s = (double)g_part[b * 512 + tid] + (double)g_part[b * 512 + tid + 256];
    __shared__ double sh[256];
    sh[tid] = s; __syncthreads();
    for (int o = 128; o > 0; o >>= 1) { if (tid < o) sh[tid] += sh[tid + o]; __syncthreads(); }
    if (tid == 0) {
        float E = (float)(T_ * SDv);
        g_mean[stage * 8 + b] = __fdiv_rn((float)sh[0], E);
    }
}

// ---------------- BN pass B: per-batch sum of (x-m)^2 -> denom ----------------
__global__ void k_redB(int sel, int SDv, int stage) {
    const float* __restrict__ X = g_ptrF[sel];
    int b = blockIdx.y;
    float m = g_mean[stage * 8 + b];
    int E = T_ * SDv;
    float s = 0.0f;
    for (int i = blockIdx.x * 256 + threadIdx.x; i < E; i += 512 * 256) {
        int t = i / SDv;
        int r = i - t * SDv;
        float v = X[(size_t)(t * B_ + b) * SDv + r] - m;
        s += v * v;
    }
    __shared__ float sh[256];
    int tid = threadIdx.x;
    sh[tid] = s; __syncthreads();
    for (int o = 128; o > 0; o >>= 1) { if (tid < o) sh[tid] += sh[tid + o]; __syncthreads(); }
    if (tid == 0) g_part[b * 512 + blockIdx.x] = sh[0];
}

__global__ void k_finB(int SDv, int stage) {
    int b = blockIdx.x, tid = threadIdx.x;
    double s = (double)g_part[b * 512 + tid] + (double)g_part[b * 512 + tid + 256];
    __shared__ double sh[256];
    sh[tid] = s; __syncthreads();
    for (int o = 128; o > 0; o >>= 1) { if (tid < o) sh[tid] += sh[tid + o]; __syncthreads(); }
    if (tid == 0) {
        float E = (float)(T_ * SDv);
        float var_f = __fdiv_rn((float)sh[0], E);
        g_denom[stage * 8 + b] = __fsqrt_rn(var_f + 1e-5f);
    }
}

// ---------------- fused BN + IF over Q,V,K with CARRIED membrane ----------------
__global__ void k_ifqvk() {
    int j = blockIdx.x * 256 + threadIdx.x;
    if (j >= BSD_) return;
    int b = j / SD_;
    float mq = g_mean[ST_Q * 8 + b], dq = g_denom[ST_Q * 8 + b];
    float mv = g_mean[ST_V * 8 + b], dv = g_denom[ST_V * 8 + b];
    float mk = g_mean[ST_K * 8 + b], dk = g_denom[ST_K * 8 + b];
    float vm = 0.0f;
#pragma unroll
    for (int t = 0; t < T_; t++) {
        int idx = t * BSD_ + j;
        vm += __fdiv_rn(g_q[idx] - mq, dq);
        float s = (vm >= 1.0f) ? 1.0f : 0.0f;
        g_qs[idx] = (u8)s;
        vm *= (1.0f - s);
    }
#pragma unroll
    for (int t = 0; t < T_; t++) {
        int idx = t * BSD_ + j;
        vm += __fdiv_rn(g_v[idx] - mv, dv);
        float s = (vm >= 1.0f) ? 1.0f : 0.0f;
        g_vs[idx] = (u8)s;
        vm *= (1.0f - s);
    }
#pragma unroll
    for (int t = 0; t < T_; t++) {
        int idx = t * BSD_ + j;
        vm += __fdiv_rn(g_k[idx] - mk, dk);
        float s = (vm >= 1.0f) ? 1.0f : 0.0f;
        g_ks[idx] = (u8)s;
        vm *= (1.0f - s);
    }
}

// ---------------- QK: integer seq-reduction (exact) ----------------
__global__ void k_qk() {
    int d = blockIdx.x * 256 + threadIdx.x;
    int tb = blockIdx.y;
    int sp = blockIdx.z;
    int acc = 0;
    int s0 = sp * 256;
    for (int s = s0; s < s0 + 256; s++) {
        size_t idx = ((size_t)tb * S_ + s) * D_ + d;
        acc += (int)(g_qs[idx] & g_ks[idx]);
    }
    g_qkp[sp * TBD_ + tb * D_ + d] = acc;
}

// QKs = IF(QK) over t (integers exact in fp32)
__global__ void k_qks() {
    int i = blockIdx.x * 256 + threadIdx.x;
    if (i >= BD_) return;
    int b = i / D_, d = i - b * D_;
    float vm = 0.0f;
#pragma unroll
    for (int t = 0; t < T_; t++) {
        int idx = (t * B_ + b) * D_ + d;
        int qk = g_qkp[idx] + g_qkp[TBD_ + idx] + g_qkp[2 * TBD_ + idx] +
                 g_qkp[3 * TBD_ + idx];
        vm += (float)qk;
        float s = (vm >= 1.0f) ? 1.0f : 0.0f;
        g_qks[idx] = (u8)s;
        vm *= (1.0f - s);
    }
}

// QKV spikes = Vs & QKs
__global__ void k_qkvm() {
    int idx = blockIdx.x * 256 + threadIdx.x;
    if (idx >= TBSD_) return;
    int d = idx % D_;
    int tb = idx / SD_;
    g_qkvm[idx] = g_vs[idx] & g_qks[tb * D_ + d];
}

// h = sp + bn(att); sp2 = IF(h)
__global__ void k_hsp2() {
    int j = blockIdx.x * 256 + threadIdx.x;
    if (j >= BSD_) return;
    int b = j / SD_;
    float m = g_mean[ST_ATT * 8 + b], dn = g_denom[ST_ATT * 8 + b];
    float vm = 0.0f;
#pragma unroll
    for (int t = 0; t < T_; t++) {
        int idx = t * BSD_ + j;
        float hval = (float)g_sp[idx] + __fdiv_rn(g_att[idx] - m, dn);
        g_h[idx] = hval;
        vm += hval;
        float s = (vm >= 1.0f) ? 1.0f : 0.0f;
        g_sp2[idx] = (u8)s;
        vm *= (1.0f - s);
    }
}

// s1 = IF(bn(o1))
__global__ void k_s1() {
    int j = blockIdx.x * 256 + threadIdx.x;
    if (j >= BSH_) return;
    int b = j / SH_;
    float m = g_mean[ST_O1 * 8 + b], dn = g_denom[ST_O1 * 8 + b];
    float vm = 0.0f;
#pragma unroll
    for (int t = 0; t < T_; t++) {
        int idx = t * BSH_ + j;
        vm += __fdiv_rn(g_o1[idx] - m, dn);
        float s = (vm >= 1.0f) ? 1.0f : 0.0f;
        g_s1[idx] = (u8)s;
        vm *= (1.0f - s);
    }
}

// out = h + bn(o2)
__global__ void k_out(float* __restrict__ out) {
    int idx = blockIdx.x * 256 + threadIdx.x;
    if (idx >= TBSD_) return;
    int b = (idx / SD_) % B_;
    float m = g_mean[ST_O2 * 8 + b], dn = g_denom[ST_O2 * 8 + b];
    out[idx] = g_h[idx] + __fdiv_rn(g_o2[idx] - m, dn);
}

// ---------------- launch (kernel launches ONLY — capture-safe) ----------------
extern "C" void kernel_launch(void* const* d_in, const int* in_sizes, int n_in,
                              void* d_out, int out_size) {
    (void)in_sizes; (void)n_in; (void)out_size;
    const float* x  = (const float*)d_in[0];
    const float* wq = (const float*)d_in[1];
    const float* wk = (const float*)d_in[2];
    const float* wv = (const float*)d_in[3];
    const float* wo = (const float*)d_in[4];
    const float* w1 = (const float*)d_in[5];
    const float* b1 = (const float*)d_in[6];
    const float* w2 = (const float*)d_in[7];
    const float* b2 = (const float*)d_in[8];
    float* out = (float*)d_out;

    const int EW = 256;
    k_init_ptrs<<<1, 32>>>();

    // 1) sp = IF(x), pack bitmask
    k_ifx<<<BSD_ / EW, EW>>>(x);
    k_pack<<<dim3(D_ / 32, MROWS_ / 8), 256>>>(0, D_ / 32);

    // 2) Q,K,V sparse GEMMs
    sgemm6<<<dim3(6, 256), 512>>>(0, wq, nullptr, 0, D_, D_);
    sgemm6<<<dim3(6, 256), 512>>>(0, wk, nullptr, 1, D_, D_);
    sgemm6<<<dim3(6, 256), 512>>>(0, wv, nullptr, 2, D_, D_);

    // 3) BN stats (two-pass) for Q, V, K
    k_redA<<<dim3(512, 8), 256>>>(0, SD_); k_finA<<<8, 256>>>(SD_, ST_Q);
    k_redB<<<dim3(512, 8), 256>>>(0, SD_, ST_Q); k_finB<<<8, 256>>>(SD_, ST_Q);
    k_redA<<<dim3(512, 8), 256>>>(2, SD_); k_finA<<<8, 256>>>(SD_, ST_V);
    k_redB<<<dim3(512, 8), 256>>>(2, SD_, ST_V); k_finB<<<8, 256>>>(SD_, ST_V);
    k_redA<<<dim3(512, 8), 256>>>(1, SD_); k_finA<<<8, 256>>>(SD_, ST_K);
    k_redB<<<dim3(512, 8), 256>>>(1, SD_, ST_K); k_finB<<<8, 256>>>(SD_, ST_K);

    // 4) fused BN+IF, membrane carried Q -> V -> K
    k_ifqvk<<<BSD_ / EW, EW>>>();

    // 5) QK (integer) + IF + QKV spikes, pack
    k_qk<<<dim3(D_ / 256, T_ * B_, 4), 256>>>();
    k_qks<<<BD_ / EW, EW>>>();
    k_qkvm<<<TBSD_ / EW, EW>>>();
    k_pack<<<dim3(D_ / 32, MROWS_ / 8), 256>>>(1, D_ / 32);

    // 6) att = QKV @ wo + BN stats
    sgemm6<<<dim3(6, 256), 512>>>(1, wo, nullptr, 3, D_, D_);
    k_redA<<<dim3(512, 8), 256>>>(3, SD_); k_finA<<<8, 256>>>(SD_, ST_ATT);
    k_redB<<<dim3(512, 8), 256>>>(3, SD_, ST_ATT); k_finB<<<8, 256>>>(SD_, ST_ATT);

    // 7) h = sp + bn(att); sp2 = IF(h), pack
    k_hsp2<<<BSD_ / EW, EW>>>();
    k_pack<<<dim3(D_ / 32, MROWS_ / 8), 256>>>(2, D_ / 32);

    // 8) o1 = sp2 @ w1 + b1; BN; s1 = IF(bn(o1)), pack
    sgemm6<<<dim3(24, 256), 512>>>(2, w1, b1, 4, HF_, D_);
    k_redA<<<dim3(512, 8), 256>>>(4, SH_); k_finA<<<8, 256>>>(SH_, ST_O1);
    k_redB<<<dim3(512, 8), 256>>>(4, SH_, ST_O1); k_finB<<<8, 256>>>(SH_, ST_O1);
    k_s1<<<BSH_ / EW, EW>>>();
    k_pack<<<dim3(HF_ / 32, MROWS_ / 8), 256>>>(3, HF_ / 32);

    // 9) o2 = s1 @ w2 + b2; BN
    sgemm6<<<dim3(6, 256), 512>>>(3, w2, b2, 5, D_, HF_);
    k_redA<<<dim3(512, 8), 256>>>(5, SD_); k_finA<<<8, 256>>>(SD_, ST_O2);
    k_redB<<<dim3(512, 8), 256>>>(5, SD_, ST_O2); k_finB<<<8, 256>>>(SD_, ST_O2);

    // 10) out = h + bn(o2)
    k_out<<<TBSD_ / EW, EW>>>(out);
}

// round 10
// speedup vs baseline: 1.0583x; 1.0583x over previous
#include <cuda_runtime.h>
#include <cstdint>

typedef unsigned long long ULL;
typedef unsigned char u8;
typedef unsigned int u32;

// ---------------- problem dims ----------------
#define T_  4
#define B_  8
#define S_  1024
#define D_  768
#define HF_ 3072
#define SD_   (S_*D_)
#define SH_   (S_*HF_)
#define BSD_  (B_*SD_)
#define BSH_  (B_*SH_)
#define TBSD_ (T_*BSD_)
#define TBSH_ (T_*BSH_)
#define TBD_  (T_*B_*D_)
#define BD_   (B_*D_)
#define MROWS_ (T_*B_*S_)

#define KC_  256   // Eigen gebp k-panel (confirmed R4)
#define KS_  32    // k per GEMM pipeline stage (1 mask word)

// bn-stat stages
#define ST_Q   0
#define ST_V   1
#define ST_K   2
#define ST_ATT 3
#define ST_O1  4
#define ST_O2  5

// ---------------- device scratch ----------------
__device__ u8    g_sp  [TBSD_];
__device__ float g_q   [TBSD_];
__device__ float g_k   [TBSD_];
__device__ float g_v   [TBSD_];
__device__ u8    g_qs  [TBSD_];
__device__ u8    g_ks  [TBSD_];
__device__ u8    g_vs  [TBSD_];
__device__ float g_att [TBSD_];
__device__ float g_h   [TBSD_];
__device__ float g_o1  [TBSH_];
__device__ float g_o2  [TBSD_];
__device__ int   g_qkp [4*TBD_];
__device__ u8    g_qks [TBD_];
__device__ float g_part[8*512];
__device__ float g_mean [6*8];
__device__ float g_denom[6*8];

// bitmasks, TRANSPOSED: [k/32][M] (contiguous in M for cp.async)
__device__ u32 g_msk_sp  [(D_/32)*MROWS_];
__device__ u32 g_msk_qkvm[(D_/32)*MROWS_];
__device__ u32 g_msk_sp2 [(D_/32)*MROWS_];
__device__ u32 g_msk_s1  [(HF_/32)*MROWS_];

// pointer tables (capture-safe: host never queries symbols)
__device__ u32*   g_ptrM[4];
__device__ float* g_ptrF[6];
__global__ void k_init_ptrs() {
    if (threadIdx.x == 0 && blockIdx.x == 0) {
        g_ptrM[0] = g_msk_sp; g_ptrM[1] = g_msk_qkvm; g_ptrM[2] = g_msk_sp2; g_ptrM[3] = g_msk_s1;
        g_ptrF[0] = g_q;   g_ptrF[1] = g_k;    g_ptrF[2] = g_v;
        g_ptrF[3] = g_att; g_ptrF[4] = g_o1;   g_ptrF[5] = g_o2;
    }
}

// ---------------- f32x2 helpers (bitwise 2x IEEE fp32 ops) ----------------
__device__ __forceinline__ ULL add2(ULL a, ULL b) {
    ULL r; asm("add.rn.f32x2 %0, %1, %2;" : "=l"(r) : "l"(a), "l"(b)); return r;
}
__device__ __forceinline__ float2 unpack2(ULL v) {
    float2 r; asm("mov.b64 {%0, %1}, %2;" : "=f"(r.x), "=f"(r.y) : "l"(v)); return r;
}

// ---------------- cp.async helpers ----------------
__device__ __forceinline__ void cp_async16(uint32_t smem, const void* g) {
    asm volatile("cp.async.cg.shared.global [%0], [%1], 16;" :: "r"(smem), "l"(g));
}
__device__ __forceinline__ void cp_commit() {
    asm volatile("cp.async.commit_group;");
}
__device__ __forceinline__ void cp_wait1() {
    asm volatile("cp.async.wait_group 1;");
}
__device__ __forceinline__ void cp_wait0() {
    asm volatile("cp.async.wait_group 0;");
}

// ---------------- sparse spike GEMM (sgemm7) ----------------
// C[M,N] = spikes(A) @ B[K,N] (+bias), A given as bitmasks MaskT[k/32][M].
// BITWISE identical to the Eigen-emulating dense chain: per output, ascending-k
// FADD of B[k][n] for set bits only; exhausted masks give __ffs(0)=0 -> smem
// row 0 which is permanently zero (+0.0 adds are exact identities). Panels of
// 256 k combined by FADD in ascending order, bias last.
// Tile 128x128, 512 threads: warp = 8 rows (processed as 4 pairs), lane = 4 cols.
__global__ __launch_bounds__(512)
void sgemm7(int aSel, const float* __restrict__ Bm, const float* __restrict__ bias,
            int cSel, int N, int K)
{
    __shared__ __align__(16) float Bs[2][34][128];  // row 0 = zeros; rows 1..32 = B slab
    __shared__ __align__(16) u32  Msm[2][128];

    const u32* __restrict__ Mt = g_ptrM[aSel];
    float* __restrict__ C = g_ptrF[cSel];

    const int tid  = threadIdx.x;
    const int wid  = tid >> 5;          // 0..15
    const int lane = tid & 31;
    const int bn = blockIdx.x, bm = blockIdx.y;
    const int lane4 = lane * 4;

    // copy mapping: 32 rows x 128 cols per stage -> smem rows 1..32
    const int crow = tid >> 4;          // 0..31
    const int cch  = (tid & 15) * 8;    // float offset, 0..120 step 8 (32B)

    uint32_t sB0 = (uint32_t)__cvta_generic_to_shared(&Bs[0][crow + 1][cch]);
    uint32_t sB1 = (uint32_t)__cvta_generic_to_shared(&Bs[1][crow + 1][cch]);
    uint32_t sM0 = (uint32_t)__cvta_generic_to_shared(&Msm[0][0]);
    uint32_t sM1 = (uint32_t)__cvta_generic_to_shared(&Msm[1][0]);

    // zero dummy row 0 of both stages
    if (tid < 128) { Bs[0][0][tid] = 0.0f; Bs[1][0][tid] = 0.0f; }

    const int S = K / KS_;

    // prologue: copy stage 0
    {
        const float* src = Bm + (size_t)crow * N + bn * 128 + cch;
        cp_async16(sB0, src);
        cp_async16(sB0 + 16, src + 4);
        if (tid < 32)
            cp_async16(sM0 + tid * 16, Mt + bm * 128 + tid * 4);
        cp_commit();
    }

    ULL acc[8][2], part[8][2];
#pragma unroll
    for (int r = 0; r < 8; r++) {
        acc[r][0] = 0ULL; acc[r][1] = 0ULL;
        part[r][0] = 0ULL; part[r][1] = 0ULL;
    }

    for (int s = 0; s < S; s++) {
        const int buf = s & 1;
        if (s + 1 < S) {
            const int k0 = (s + 1) * KS_;
            const float* src = Bm + (size_t)(k0 + crow) * N + bn * 128 + cch;
            uint32_t dB = buf ? sB0 : sB1;
            cp_async16(dB, src);
            cp_async16(dB + 16, src + 4);
            if (tid < 32)
                cp_async16((buf ? sM0 : sM1) + tid * 16,
                           Mt + (size_t)(s + 1) * MROWS_ + bm * 128 + tid * 4);
            cp_commit();
            cp_wait1();
        } else {
            cp_wait0();
        }
        __syncthreads();

#pragma unroll
        for (int rp = 0; rp < 4; rp++) {
            u32 w0 = Msm[buf][wid * 8 + 2 * rp];
            u32 w1 = Msm[buf][wid * 8 + 2 * rp + 1];
            int p0c = __popc(w0), p1c = __popc(w1);
            int n = ((p0c > p1c ? p0c : p1c) + 3) >> 2;
            ULL a00 = part[2 * rp][0],     a01 = part[2 * rp][1];
            ULL a10 = part[2 * rp + 1][0], a11 = part[2 * rp + 1][1];
            for (int it = 0; it < n; it++) {
#pragma unroll
                for (int u = 0; u < 4; u++) {
                    int k0 = __ffs(w0); w0 &= w0 - 1;   // 0 -> zero row (+0.0)
                    int k1 = __ffs(w1); w1 &= w1 - 1;
                    ulonglong2 v0 = *(const ulonglong2*)&Bs[buf][k0][lane4];
                    ulonglong2 v1 = *(const ulonglong2*)&Bs[buf][k1][lane4];
                    a00 = add2(a00, v0.x); a01 = add2(a01, v0.y);
                    a10 = add2(a10, v1.x); a11 = add2(a11, v1.y);
                }
            }
            part[2 * rp][0] = a00;     part[2 * rp][1] = a01;
            part[2 * rp + 1][0] = a10; part[2 * rp + 1][1] = a11;
        }
        __syncthreads();   // protect buf from next iteration's copy

        // Eigen panel boundary (every 256 k): FADD-flush part into acc
        if (((s + 1) & 7) == 0) {
#pragma unroll
            for (int r = 0; r < 8; r++) {
                acc[r][0] = add2(acc[r][0], part[r][0]); part[r][0] = 0ULL;
                acc[r][1] = add2(acc[r][1], part[r][1]); part[r][1] = 0ULL;
            }
        }
    }

    float bb[4];
#pragma unroll
    for (int j = 0; j < 4; j++)
        bb[j] = bias ? bias[bn * 128 + lane4 + j] : 0.0f;

#pragma unroll
    for (int r = 0; r < 8; r++) {
        int row = bm * 128 + wid * 8 + r;
        float2 q0 = unpack2(acc[r][0]), q1 = unpack2(acc[r][1]);
        *(float4*)(C + (size_t)row * N + bn * 128 + lane4) =
            make_float4(q0.x + bb[0], q0.y + bb[1], q1.x + bb[2], q1.y + bb[3]);
    }
}

// ---------------- IF on input x -> sp bytes + fused mask pack ----------------
__global__ void k_ifx(const float* __restrict__ x) {
    int j = blockIdx.x * 256 + threadIdx.x;
    if (j >= BSD_) return;
    int lane = threadIdx.x & 31;
    int row = j / D_;              // b*S + s
    int kw  = (j % D_) >> 5;
    float vm = 0.0f;
#pragma unroll
    for (int t = 0; t < T_; t++) {
        int idx = t * BSD_ + j;
        vm += x[idx];
        float s = (vm >= 1.0f) ? 1.0f : 0.0f;
        u8 sb = (u8)s;
        g_sp[idx] = sb;
        u32 bal = __ballot_sync(0xffffffffu, sb != 0);
        if (lane == 0) g_msk_sp[(size_t)kw * MROWS_ + t * (B_ * S_) + row] = bal;
        vm *= (1.0f - s);
    }
}

// ---------------- BN pass A: per-batch sum -> mean ----------------
__global__ void k_redA(int sel, int SDv) {
    const float* __restrict__ X = g_ptrF[sel];
    int b = blockIdx.y;
    int E = T_ * SDv;
    float s = 0.0f;
    for (int i = blockIdx.x * 256 + threadIdx.x; i < E; i += 512 * 256) {
        int t = i / SDv;
        int r = i - t * SDv;
        s += X[(size_t)(t * B_ + b) * SDv + r];
    }
    __shared__ float sh[256];
    int tid = threadIdx.x;
    sh[tid] = s; __syncthreads();
    for (int o = 128; o > 0; o >>= 1) { if (tid < o) sh[tid] += sh[tid + o]; __syncthreads(); }
    if (tid == 0) g_part[b * 512 + blockIdx.x] = sh[0];
}

__global__ void k_finA(int SDv, int stage) {
    int b = blockIdx.x, tid = threadIdx.x;
    double s = (double)g_part[b * 512 + tid] + (double)g_part[b * 512 + tid + 256];
    __shared__ double sh[256];
    sh[tid] = s; __syncthreads();
    for (int o = 128; o > 0; o >>= 1) { if (tid < o) sh[tid] += sh[tid + o]; __syncthreads(); }
    if (tid == 0) {
        float E = (float)(T_ * SDv);
        g_mean[stage * 8 + b] = __fdiv_rn((float)sh[0], E);
    }
}

// ---------------- BN pass B: per-batch sum of (x-m)^2 -> denom ----------------
__global__ void k_redB(int sel, int SDv, int stage) {
    const float* __restrict__ X = g_ptrF[sel];
    int b = blockIdx.y;
    float m = g_mean[stage * 8 + b];
    int E = T_ * SDv;
    float s = 0.0f;
    for (int i = blockIdx.x * 256 + threadIdx.x; i < E; i += 512 * 256) {
        int t = i / SDv;
        int r = i - t * SDv;
        float v = X[(size_t)(t * B_ + b) * SDv + r] - m;
        s += v * v;
    }
    __shared__ float sh[256];
    int tid = threadIdx.x;
    sh[tid] = s; __syncthreads();
    for (int o = 128; o > 0; o >>= 1) { if (tid < o) sh[tid] += sh[tid + o]; __syncthreads(); }
    if (tid == 0) g_part[b * 512 + blockIdx.x] = sh[0];
}

__global__ void k_finB(int SDv, int stage) {
    int b = blockIdx.x, tid = threadIdx.x;
    double s = (double)g_part[b * 512 + tid] + (double)g_part[b * 512 + tid + 256];
    __shared__ double sh[256];
    sh[tid] = s; __syncthreads();
    for (int o = 128; o > 0; o >>= 1) { if (tid < o) sh[tid] += sh[tid + o]; __syncthreads(); }
    if (tid == 0) {
        float E = (float)(T_ * SDv);
        float var_f = __fdiv_rn((float)sh[0], E);
        g_denom[stage * 8 + b] = __fsqrt_rn(var_f + 1e-5f);
    }
}

// ---------------- fused BN + IF over Q,V,K with CARRIED membrane ----------------
__global__ void k_ifqvk() {
    int j = blockIdx.x * 256 + threadIdx.x;
    if (j >= BSD_) return;
    int b = j / SD_;
    float mq = g_mean[ST_Q * 8 + b], dq = g_denom[ST_Q * 8 + b];
    float mv = g_mean[ST_V * 8 + b], dv = g_denom[ST_V * 8 + b];
    float mk = g_mean[ST_K * 8 + b], dk = g_denom[ST_K * 8 + b];
    float vm = 0.0f;
#pragma unroll
    for (int t = 0; t < T_; t++) {
        int idx = t * BSD_ + j;
        vm += __fdiv_rn(g_q[idx] - mq, dq);
        float s = (vm >= 1.0f) ? 1.0f : 0.0f;
        g_qs[idx] = (u8)s;
        vm *= (1.0f - s);
    }
#pragma unroll
    for (int t = 0; t < T_; t++) {
        int idx = t * BSD_ + j;
        vm += __fdiv_rn(g_v[idx] - mv, dv);
        float s = (vm >= 1.0f) ? 1.0f : 0.0f;
        g_vs[idx] = (u8)s;
        vm *= (1.0f - s);
    }
#pragma unroll
    for (int t = 0; t < T_; t++) {
        int idx = t * BSD_ + j;
        vm += __fdiv_rn(g_k[idx] - mk, dk);
        float s = (vm >= 1.0f) ? 1.0f : 0.0f;
        g_ks[idx] = (u8)s;
        vm *= (1.0f - s);
    }
}

// ---------------- QK: integer seq-reduction (exact) ----------------
__global__ void k_qk() {
    int d = blockIdx.x * 256 + threadIdx.x;
    int tb = blockIdx.y;
    int sp = blockIdx.z;
    int acc = 0;
    int s0 = sp * 256;
    for (int s = s0; s < s0 + 256; s++) {
        size_t idx = ((size_t)tb * S_ + s) * D_ + d;
        acc += (int)(g_qs[idx] & g_ks[idx]);
    }
    g_qkp[sp * TBD_ + tb * D_ + d] = acc;
}

// QKs = IF(QK) over t (integers exact in fp32)
__global__ void k_qks() {
    int i = blockIdx.x * 256 + threadIdx.x;
    if (i >= BD_) return;
    int b = i / D_, d = i - b * D_;
    float vm = 0.0f;
#pragma unroll
    for (int t = 0; t < T_; t++) {
        int idx = (t * B_ + b) * D_ + d;
        int qk = g_qkp[idx] + g_qkp[TBD_ + idx] + g_qkp[2 * TBD_ + idx] +
                 g_qkp[3 * TBD_ + idx];
        vm += (float)qk;
        float s = (vm >= 1.0f) ? 1.0f : 0.0f;
        g_qks[idx] = (u8)s;
        vm *= (1.0f - s);
    }
}

// QKV spikes = Vs & QKs, mask emitted directly (no byte array consumer)
__global__ void k_qkvm() {
    int idx = blockIdx.x * 256 + threadIdx.x;
    if (idx >= TBSD_) return;
    int lane = threadIdx.x & 31;
    int d = idx % D_;
    int tb = idx / SD_;           // t*B + b
    u8 v = g_vs[idx] & g_qks[tb * D_ + d];
    u32 bal = __ballot_sync(0xffffffffu, v != 0);
    if (lane == 0) {
        int m = idx / D_;         // == t*B*S + b*S + s
        int kw = d >> 5;
        g_msk_qkvm[(size_t)kw * MROWS_ + m] = bal;
    }
}

// h = sp + bn(att); sp2 = IF(h), mask emitted directly
__global__ void k_hsp2() {
    int j = blockIdx.x * 256 + threadIdx.x;
    if (j >= BSD_) return;
    int lane = threadIdx.x & 31;
    int b = j / SD_;
    int row = j / D_;
    int kw = (j % D_) >> 5;
    float m = g_mean[ST_ATT * 8 + b], dn = g_denom[ST_ATT * 8 + b];
    float vm = 0.0f;
#pragma unroll
    for (int t = 0; t < T_; t++) {
        int idx = t * BSD_ + j;
        float hval = (float)g_sp[idx] + __fdiv_rn(g_att[idx] - m, dn);
        g_h[idx] = hval;
        vm += hval;
        float s = (vm >= 1.0f) ? 1.0f : 0.0f;
        u32 bal = __ballot_sync(0xffffffffu, s != 0.0f);
        if (lane == 0) g_msk_sp2[(size_t)kw * MROWS_ + t * (B_ * S_) + row] = bal;
        vm *= (1.0f - s);
    }
}

// s1 = IF(bn(o1)), mask emitted directly
__global__ void k_s1() {
    int j = blockIdx.x * 256 + threadIdx.x;
    if (j >= BSH_) return;
    int lane = threadIdx.x & 31;
    int b = j / SH_;
    int row = j / HF_;
    int kw = (j % HF_) >> 5;
    float m = g_mean[ST_O1 * 8 + b], dn = g_denom[ST_O1 * 8 + b];
    float vm = 0.0f;
#pragma unroll
    for (int t = 0; t < T_; t++) {
        int idx = t * BSH_ + j;
        vm += __fdiv_rn(g_o1[idx] - m, dn);
        float s = (vm >= 1.0f) ? 1.0f : 0.0f;
        u32 bal = __ballot_sync(0xffffffffu, s != 0.0f);
        if (lane == 0) g_msk_s1[(size_t)kw * MROWS_ + t * (B_ * S_) + row] = bal;
        vm *= (1.0f - s);
    }
}

// out = h + bn(o2)
__global__ void k_out(float* __restrict__ out) {
    int idx = blockIdx.x * 256 + threadIdx.x;
    if (idx >= TBSD_) return;
    int b = (idx / SD_) % B_;
    float m = g_mean[ST_O2 * 8 + b], dn = g_denom[ST_O2 * 8 + b];
    out[idx] = g_h[idx] + __fdiv_rn(g_o2[idx] - m, dn);
}

// ---------------- launch (kernel launches ONLY — capture-safe) ----------------
extern "C" void kernel_launch(void* const* d_in, const int* in_sizes, int n_in,
                              void* d_out, int out_size) {
    (void)in_sizes; (void)n_in; (void)out_size;
    const float* x  = (const float*)d_in[0];
    const float* wq = (const float*)d_in[1];
    const float* wk = (const float*)d_in[2];
    const float* wv = (const float*)d_in[3];
    const float* wo = (const float*)d_in[4];
    const float* w1 = (const float*)d_in[5];
    const float* b1 = (const float*)d_in[6];
    const float* w2 = (const float*)d_in[7];
    const float* b2 = (const float*)d_in[8];
    float* out = (float*)d_out;

    const int EW = 256;
    k_init_ptrs<<<1, 32>>>();

    // 1) sp = IF(x) + mask pack (fused)
    k_ifx<<<BSD_ / EW, EW>>>(x);

    // 2) Q,K,V sparse GEMMs
    sgemm7<<<dim3(6, 256), 512>>>(0, wq, nullptr, 0, D_, D_);
    sgemm7<<<dim3(6, 256), 512>>>(0, wk, nullptr, 1, D_, D_);
    sgemm7<<<dim3(6, 256), 512>>>(0, wv, nullptr, 2, D_, D_);

    // 3) BN stats (two-pass) for Q, V, K
    k_redA<<<dim3(512, 8), 256>>>(0, SD_); k_finA<<<8, 256>>>(SD_, ST_Q);
    k_redB<<<dim3(512, 8), 256>>>(0, SD_, ST_Q); k_finB<<<8, 256>>>(SD_, ST_Q);
    k_redA<<<dim3(512, 8), 256>>>(2, SD_); k_finA<<<8, 256>>>(SD_, ST_V);
    k_redB<<<dim3(512, 8), 256>>>(2, SD_, ST_V); k_finB<<<8, 256>>>(SD_, ST_V);
    k_redA<<<dim3(512, 8), 256>>>(1, SD_); k_finA<<<8, 256>>>(SD_, ST_K);
    k_redB<<<dim3(512, 8), 256>>>(1, SD_, ST_K); k_finB<<<8, 256>>>(SD_, ST_K);

    // 4) fused BN+IF, membrane carried Q -> V -> K
    k_ifqvk<<<BSD_ / EW, EW>>>();

    // 5) QK (integer) + IF + QKV spike mask (fused pack)
    k_qk<<<dim3(D_ / 256, T_ * B_, 4), 256>>>();
    k_qks<<<BD_ / EW, EW>>>();
    k_qkvm<<<TBSD_ / EW, EW>>>();

    // 6) att = QKV @ wo + BN stats
    sgemm7<<<dim3(6, 256), 512>>>(1, wo, nullptr, 3, D_, D_);
    k_redA<<<dim3(512, 8), 256>>>(3, SD_); k_finA<<<8, 256>>>(SD_, ST_ATT);
    k_redB<<<dim3(512, 8), 256>>>(3, SD_, ST_ATT); k_finB<<<8, 256>>>(SD_, ST_ATT);

    // 7) h = sp + bn(att); sp2 = IF(h) + mask pack (fused)
    k_hsp2<<<BSD_ / EW, EW>>>();

    // 8) o1 = sp2 @ w1 + b1; BN; s1 = IF(bn(o1)) + mask pack (fused)
    sgemm7<<<dim3(24, 256), 512>>>(2, w1, b1, 4, HF_, D_);
    k_redA<<<dim3(512, 8), 256>>>(4, SH_); k_finA<<<8, 256>>>(SH_, ST_O1);
    k_redB<<<dim3(512, 8), 256>>>(4, SH_, ST_O1); k_finB<<<8, 256>>>(SH_, ST_O1);
    k_s1<<<BSH_ / EW, EW>>>();

    // 9) o2 = s1 @ w2 + b2; BN
    sgemm7<<<dim3(6, 256), 512>>>(3, w2, b2, 5, D_, HF_);
    k_redA<<<dim3(512, 8), 256>>>(5, SD_); k_finA<<<8, 256>>>(SD_, ST_O2);
    k_redB<<<dim3(512, 8), 256>>>(5, SD_, ST_O2); k_finB<<<8, 256>>>(SD_, ST_O2);

    // 10) out = h + bn(o2)
    k_out<<<TBSD_ / EW, EW>>>(out);
}

// round 12
// speedup vs baseline: 1.1996x; 1.1335x over previous
#include <cuda_runtime.h>
#include <cstdint>

typedef unsigned long long ULL;
typedef unsigned char u8;
typedef unsigned int u32;

// ---------------- problem dims ----------------
#define T_  4
#define B_  8
#define S_  1024
#define D_  768
#define HF_ 3072
#define SD_   (S_*D_)
#define SH_   (S_*HF_)
#define BSD_  (B_*SD_)
#define BSH_  (B_*SH_)
#define TBSD_ (T_*BSD_)
#define TBSH_ (T_*BSH_)
#define TBD_  (T_*B_*D_)
#define BD_   (B_*D_)
#define MROWS_ (T_*B_*S_)

#define KC_  256   // Eigen gebp k-panel (confirmed R4)
#define KS_  32    // k per GEMM pipeline stage (1 mask word)

// bn-stat stages
#define ST_Q   0
#define ST_V   1
#define ST_K   2
#define ST_ATT 3
#define ST_O1  4
#define ST_O2  5

// ---------------- device scratch ----------------
__device__ u8    g_sp  [TBSD_];
__device__ float g_q   [TBSD_];
__device__ float g_k   [TBSD_];
__device__ float g_v   [TBSD_];
__device__ u8    g_qs  [TBSD_];
__device__ u8    g_ks  [TBSD_];
__device__ u8    g_vs  [TBSD_];
__device__ float g_att [TBSD_];
__device__ float g_h   [TBSD_];
__device__ float g_o1  [TBSH_];
__device__ float g_o2  [TBSD_];
__device__ int   g_qkp [4*TBD_];
__device__ u8    g_qks [TBD_];
__device__ float g_part[8*512];
__device__ float g_mean [6*8];
__device__ float g_denom[6*8];

// bitmasks, TRANSPOSED: [k/32][M] (contiguous in M for cp.async)
__device__ u32 g_msk_sp  [(D_/32)*MROWS_];
__device__ u32 g_msk_qkvm[(D_/32)*MROWS_];
__device__ u32 g_msk_sp2 [(D_/32)*MROWS_];
__device__ u32 g_msk_s1  [(HF_/32)*MROWS_];

// pointer tables (capture-safe: host never queries symbols)
__device__ u32*   g_ptrM[4];
__device__ float* g_ptrF[6];
__global__ void k_init_ptrs() {
    if (threadIdx.x == 0 && blockIdx.x == 0) {
        g_ptrM[0] = g_msk_sp; g_ptrM[1] = g_msk_qkvm; g_ptrM[2] = g_msk_sp2; g_ptrM[3] = g_msk_s1;
        g_ptrF[0] = g_q;   g_ptrF[1] = g_k;    g_ptrF[2] = g_v;
        g_ptrF[3] = g_att; g_ptrF[4] = g_o1;   g_ptrF[5] = g_o2;
    }
}

// ---------------- f32x2 helpers (bitwise 2x IEEE fp32 ops) ----------------
__device__ __forceinline__ ULL add2(ULL a, ULL b) {
    ULL r; asm("add.rn.f32x2 %0, %1, %2;" : "=l"(r) : "l"(a), "l"(b)); return r;
}
__device__ __forceinline__ float2 unpack2(ULL v) {
    float2 r; asm("mov.b64 {%0, %1}, %2;" : "=f"(r.x), "=f"(r.y) : "l"(v)); return r;
}

// ---------------- cp.async helpers ----------------
__device__ __forceinline__ void cp_async16(uint32_t smem, const void* g) {
    asm volatile("cp.async.cg.shared.global [%0], [%1], 16;" :: "r"(smem), "l"(g));
}
__device__ __forceinline__ void cp_commit() {
    asm volatile("cp.async.commit_group;");
}
__device__ __forceinline__ void cp_wait1() {
    asm volatile("cp.async.wait_group 1;");
}
__device__ __forceinline__ void cp_wait0() {
    asm volatile("cp.async.wait_group 0;");
}

// ---------------- sparse spike GEMM (sgemm8) ----------------
// C[M,N] = spikes(A) @ B[K,N] (+bias), A given as bitmasks MaskT[k/32][M].
// BITWISE identical to the Eigen-emulating dense chain: per output, ascending-k
// FADD of B[k][n] for set bits only; exhausted masks give __ffs(0)=0 -> smem
// row 0 which is permanently zero (+0.0 adds are exact identities). Panels of
// 256 k combined by FADD in ascending order, bias last.
// Tile 64x128, 512 threads: warp = 4 rows (2 pairs), lane = 4 cols.
// 4-rows/warp halves register state -> 2 blocks/SM (32 warps) for latency cover.
__global__ __launch_bounds__(512, 2)
void sgemm8(int aSel, const float* __restrict__ Bm, const float* __restrict__ bias,
            int cSel, int N, int K)
{
    __shared__ __align__(16) float Bs[2][34][128];  // row 0 = zeros; rows 1..32 = B slab
    __shared__ __align__(16) u32  Msm[2][64];

    const u32* __restrict__ Mt = g_ptrM[aSel];
    float* __restrict__ C = g_ptrF[cSel];

    const int tid  = threadIdx.x;
    const int wid  = tid >> 5;          // 0..15
    const int lane = tid & 31;
    const int bn = blockIdx.x, bm = blockIdx.y;
    const int lane4 = lane * 4;

    // copy mapping: 32 rows x 128 cols per stage -> smem rows 1..32
    const int crow = tid >> 4;          // 0..31
    const int cch  = (tid & 15) * 8;    // float offset, 0..120 step 8 (32B)

    uint32_t sB0 = (uint32_t)__cvta_generic_to_shared(&Bs[0][crow + 1][cch]);
    uint32_t sB1 = (uint32_t)__cvta_generic_to_shared(&Bs[1][crow + 1][cch]);
    uint32_t sM0 = (uint32_t)__cvta_generic_to_shared(&Msm[0][0]);
    uint32_t sM1 = (uint32_t)__cvta_generic_to_shared(&Msm[1][0]);

    // zero dummy row 0 of both stages
    if (tid < 128) { Bs[0][0][tid] = 0.0f; Bs[1][0][tid] = 0.0f; }

    const int S = K / KS_;

    // prologue: copy stage 0
    {
        const float* src = Bm + (size_t)crow * N + bn * 128 + cch;
        cp_async16(sB0, src);
        cp_async16(sB0 + 16, src + 4);
        if (tid < 16)
            cp_async16(sM0 + tid * 16, Mt + bm * 64 + tid * 4);
        cp_commit();
    }

    ULL acc[4][2], part[4][2];
#pragma unroll
    for (int r = 0; r < 4; r++) {
        acc[r][0] = 0ULL; acc[r][1] = 0ULL;
        part[r][0] = 0ULL; part[r][1] = 0ULL;
    }

    for (int s = 0; s < S; s++) {
        const int buf = s & 1;
        if (s + 1 < S) {
            const int k0 = (s + 1) * KS_;
            const float* src = Bm + (size_t)(k0 + crow) * N + bn * 128 + cch;
            uint32_t dB = buf ? sB0 : sB1;
            cp_async16(dB, src);
            cp_async16(dB + 16, src + 4);
            if (tid < 16)
                cp_async16((buf ? sM0 : sM1) + tid * 16,
                           Mt + (size_t)(s + 1) * MROWS_ + bm * 64 + tid * 4);
            cp_commit();
            cp_wait1();
        } else {
            cp_wait0();
        }
        __syncthreads();

#pragma unroll
        for (int rp = 0; rp < 2; rp++) {
            u32 w0 = Msm[buf][wid * 4 + 2 * rp];
            u32 w1 = Msm[buf][wid * 4 + 2 * rp + 1];
            int p0c = __popc(w0), p1c = __popc(w1);
            int n = ((p0c > p1c ? p0c : p1c) + 3) >> 2;
            ULL a00 = part[2 * rp][0],     a01 = part[2 * rp][1];
            ULL a10 = part[2 * rp + 1][0], a11 = part[2 * rp + 1][1];
            for (int it = 0; it < n; it++) {
#pragma unroll
                for (int u = 0; u < 4; u++) {
                    int k0 = __ffs(w0); w0 &= w0 - 1;   // 0 -> zero row (+0.0)
                    int k1 = __ffs(w1); w1 &= w1 - 1;
                    ulonglong2 v0 = *(const ulonglong2*)&Bs[buf][k0][lane4];
                    ulonglong2 v1 = *(const ulonglong2*)&Bs[buf][k1][lane4];
                    a00 = add2(a00, v0.x); a01 = add2(a01, v0.y);
                    a10 = add2(a10, v1.x); a11 = add2(a11, v1.y);
                }
            }
            part[2 * rp][0] = a00;     part[2 * rp][1] = a01;
            part[2 * rp + 1][0] = a10; part[2 * rp + 1][1] = a11;
        }
        __syncthreads();   // protect buf from next iteration's copy

        // Eigen panel boundary (every 256 k): FADD-flush part into acc
        if (((s + 1) & 7) == 0) {
#pragma unroll
            for (int r = 0; r < 4; r++) {
                acc[r][0] = add2(acc[r][0], part[r][0]); part[r][0] = 0ULL;
                acc[r][1] = add2(acc[r][1], part[r][1]); part[r][1] = 0ULL;
            }
        }
    }

    float bb[4];
#pragma unroll
    for (int j = 0; j < 4; j++)
        bb[j] = bias ? bias[bn * 128 + lane4 + j] : 0.0f;

#pragma unroll
    for (int r = 0; r < 4; r++) {
        int row = bm * 64 + wid * 4 + r;
        float2 q0 = unpack2(acc[r][0]), q1 = unpack2(acc[r][1]);
        *(float4*)(C + (size_t)row * N + bn * 128 + lane4) =
            make_float4(q0.x + bb[0], q0.y + bb[1], q1.x + bb[2], q1.y + bb[3]);
    }
}

// ---------------- IF on input x -> sp bytes + fused mask pack ----------------
__global__ void k_ifx(const float* __restrict__ x) {
    int j = blockIdx.x * 256 + threadIdx.x;
    if (j >= BSD_) return;
    int lane = threadIdx.x & 31;
    int row = j / D_;              // b*S + s
    int kw  = (j % D_) >> 5;
    float vm = 0.0f;
#pragma unroll
    for (int t = 0; t < T_; t++) {
        int idx = t * BSD_ + j;
        vm += x[idx];
        float s = (vm >= 1.0f) ? 1.0f : 0.0f;
        u8 sb = (u8)s;
        g_sp[idx] = sb;
        u32 bal = __ballot_sync(0xffffffffu, sb != 0);
        if (lane == 0) g_msk_sp[(size_t)kw * MROWS_ + t * (B_ * S_) + row] = bal;
        vm *= (1.0f - s);
    }
}

// ---------------- BN pass A: per-batch sum -> mean ----------------
__global__ void k_redA(int sel, int SDv) {
    const float* __restrict__ X = g_ptrF[sel];
    int b = blockIdx.y;
    int E = T_ * SDv;
    float s = 0.0f;
    for (int i = blockIdx.x * 256 + threadIdx.x; i < E; i += 512 * 256) {
        int t = i / SDv;
        int r = i - t * SDv;
        s += X[(size_t)(t * B_ + b) * SDv + r];
    }
    __shared__ float sh[256];
    int tid = threadIdx.x;
    sh[tid] = s; __syncthreads();
    for (int o = 128; o > 0; o >>= 1) { if (tid < o) sh[tid] += sh[tid + o]; __syncthreads(); }
    if (tid == 0) g_part[b * 512 + blockIdx.x] = sh[0];
}

__global__ void k_finA(int SDv, int stage) {
    int b = blockIdx.x, tid = threadIdx.x;
    double s = (double)g_part[b * 512 + tid] + (double)g_part[b * 512 + tid + 256];
    __shared__ double sh[256];
    sh[tid] = s; __syncthreads();
    for (int o = 128; o > 0; o >>= 1) { if (tid < o) sh[tid] += sh[tid + o]; __syncthreads(); }
    if (tid == 0) {
        float E = (float)(T_ * SDv);
        g_mean[stage * 8 + b] = __fdiv_rn((float)sh[0], E);
    }
}

// ---------------- BN pass B: per-batch sum of (x-m)^2 -> denom ----------------
__global__ void k_redB(int sel, int SDv, int stage) {
    const float* __restrict__ X = g_ptrF[sel];
    int b = blockIdx.y;
    float m = g_mean[stage * 8 + b];
    int E = T_ * SDv;
    float s = 0.0f;
    for (int i = blockIdx.x * 256 + threadIdx.x; i < E; i += 512 * 256) {
        int t = i / SDv;
        int r = i - t * SDv;
        float v = X[(size_t)(t * B_ + b) * SDv + r] - m;
        s += v * v;
    }
    __shared__ float sh[256];
    int tid = threadIdx.x;
    sh[tid] = s; __syncthreads();
    for (int o = 128; o > 0; o >>= 1) { if (tid < o) sh[tid] += sh[tid + o]; __syncthreads(); }
    if (tid == 0) g_part[b * 512 + blockIdx.x] = sh[0];
}

__global__ void k_finB(int SDv, int stage) {
    int b = blockIdx.x, tid = threadIdx.x;
    double s = (double)g_part[b * 512 + tid] + (double)g_part[b * 512 + tid + 256];
    __shared__ double sh[256];
    sh[tid] = s; __syncthreads();
    for (int o = 128; o > 0; o >>= 1) { if (tid < o) sh[tid] += sh[tid + o]; __syncthreads(); }
    if (tid == 0) {
        float E = (float)(T_ * SDv);
        float var_f = __fdiv_rn((float)sh[0], E);
        g_denom[stage * 8 + b] = __fsqrt_rn(var_f + 1e-5f);
    }
}

// ---------------- fused BN + IF over Q,V,K with CARRIED membrane ----------------
__global__ void k_ifqvk() {
    int j = blockIdx.x * 256 + threadIdx.x;
    if (j >= BSD_) return;
    int b = j / SD_;
    float mq = g_mean[ST_Q * 8 + b], dq = g_denom[ST_Q * 8 + b];
    float mv = g_mean[ST_V * 8 + b], dv = g_denom[ST_V * 8 + b];
    float mk = g_mean[ST_K * 8 + b], dk = g_denom[ST_K * 8 + b];
    float vm = 0.0f;
#pragma unroll
    for (int t = 0; t < T_; t++) {
        int idx = t * BSD_ + j;
        vm += __fdiv_rn(g_q[idx] - mq, dq);
        float s = (vm >= 1.0f) ? 1.0f : 0.0f;
        g_qs[idx] = (u8)s;
        vm *= (1.0f - s);
    }
#pragma unroll
    for (int t = 0; t < T_; t++) {
        int idx = t * BSD_ + j;
        vm += __fdiv_rn(g_v[idx] - mv, dv);
        float s = (vm >= 1.0f) ? 1.0f : 0.0f;
        g_vs[idx] = (u8)s;
        vm *= (1.0f - s);
    }
#pragma unroll
    for (int t = 0; t < T_; t++) {
        int idx = t * BSD_ + j;
        vm += __fdiv_rn(g_k[idx] - mk, dk);
        float s = (vm >= 1.0f) ? 1.0f : 0.0f;
        g_ks[idx] = (u8)s;
        vm *= (1.0f - s);
    }
}

// ---------------- QK: integer seq-reduction (exact) ----------------
__global__ void k_qk() {
    int d = blockIdx.x * 256 + threadIdx.x;
    int tb = blockIdx.y;
    int sp = blockIdx.z;
    int acc = 0;
    int s0 = sp * 256;
    for (int s = s0; s < s0 + 256; s++) {
        size_t idx = ((size_t)tb * S_ + s) * D_ + d;
        acc += (int)(g_qs[idx] & g_ks[idx]);
    }
    g_qkp[sp * TBD_ + tb * D_ + d] = acc;
}

// QKs = IF(QK) over t (integers exact in fp32)
__global__ void k_qks() {
    int i = blockIdx.x * 256 + threadIdx.x;
    if (i >= BD_) return;
    int b = i / D_, d = i - b * D_;
    float vm = 0.0f;
#pragma unroll
    for (int t = 0; t < T_; t++) {
        int idx = (t * B_ + b) * D_ + d;
        int qk = g_qkp[idx] + g_qkp[TBD_ + idx] + g_qkp[2 * TBD_ + idx] +
                 g_qkp[3 * TBD_ + idx];
        vm += (float)qk;
        float s = (vm >= 1.0f) ? 1.0f : 0.0f;
        g_qks[idx] = (u8)s;
        vm *= (1.0f - s);
    }
}

// QKV spikes = Vs & QKs, mask emitted directly
__global__ void k_qkvm() {
    int idx = blockIdx.x * 256 + threadIdx.x;
    if (idx >= TBSD_) return;
    int lane = threadIdx.x & 31;
    int d = idx % D_;
    int tb = idx / SD_;           // t*B + b
    u8 v = g_vs[idx] & g_qks[tb * D_ + d];
    u32 bal = __ballot_sync(0xffffffffu, v != 0);
    if (lane == 0) {
        int m = idx / D_;         // == t*B*S + b*S + s
        int kw = d >> 5;
        g_msk_qkvm[(size_t)kw * MROWS_ + m] = bal;
    }
}

// h = sp + bn(att); sp2 = IF(h), mask emitted directly
__global__ void k_hsp2() {
    int j = blockIdx.x * 256 + threadIdx.x;
    if (j >= BSD_) return;
    int lane = threadIdx.x & 31;
    int b = j / SD_;
    int row = j / D_;
    int kw = (j % D_) >> 5;
    float m = g_mean[ST_ATT * 8 + b], dn = g_denom[ST_ATT * 8 + b];
    float vm = 0.0f;
#pragma unroll
    for (int t = 0; t < T_; t++) {
        int idx = t * BSD_ + j;
        float hval = (float)g_sp[idx] + __fdiv_rn(g_att[idx] - m, dn);
        g_h[idx] = hval;
        vm += hval;
        float s = (vm >= 1.0f) ? 1.0f : 0.0f;
        u32 bal = __ballot_sync(0xffffffffu, s != 0.0f);
        if (lane == 0) g_msk_sp2[(size_t)kw * MROWS_ + t * (B_ * S_) + row] = bal;
        vm *= (1.0f - s);
    }
}

// s1 = IF(bn(o1)), mask emitted directly
__global__ void k_s1() {
    int j = blockIdx.x * 256 + threadIdx.x;
    if (j >= BSH_) return;
    int lane = threadIdx.x & 31;
    int b = j / SH_;
    int row = j / HF_;
    int kw = (j % HF_) >> 5;
    float m = g_mean[ST_O1 * 8 + b], dn = g_denom[ST_O1 * 8 + b];
    float vm = 0.0f;
#pragma unroll
    for (int t = 0; t < T_; t++) {
        int idx = t * BSH_ + j;
        vm += __fdiv_rn(g_o1[idx] - m, dn);
        float s = (vm >= 1.0f) ? 1.0f : 0.0f;
        u32 bal = __ballot_sync(0xffffffffu, s != 0.0f);
        if (lane == 0) g_msk_s1[(size_t)kw * MROWS_ + t * (B_ * S_) + row] = bal;
        vm *= (1.0f - s);
    }
}

// out = h + bn(o2)
__global__ void k_out(float* __restrict__ out) {
    int idx = blockIdx.x * 256 + threadIdx.x;
    if (idx >= TBSD_) return;
    int b = (idx / SD_) % B_;
    float m = g_mean[ST_O2 * 8 + b], dn = g_denom[ST_O2 * 8 + b];
    out[idx] = g_h[idx] + __fdiv_rn(g_o2[idx] - m, dn);
}

// ---------------- launch (kernel launches ONLY — capture-safe) ----------------
extern "C" void kernel_launch(void* const* d_in, const int* in_sizes, int n_in,
                              void* d_out, int out_size) {
    (void)in_sizes; (void)n_in; (void)out_size;
    const float* x  = (const float*)d_in[0];
    const float* wq = (const float*)d_in[1];
    const float* wk = (const float*)d_in[2];
    const float* wv = (const float*)d_in[3];
    const float* wo = (const float*)d_in[4];
    const float* w1 = (const float*)d_in[5];
    const float* b1 = (const float*)d_in[6];
    const float* w2 = (const float*)d_in[7];
    const float* b2 = (const float*)d_in[8];
    float* out = (float*)d_out;

    const int EW = 256;
    k_init_ptrs<<<1, 32>>>();

    // 1) sp = IF(x) + mask pack (fused)
    k_ifx<<<BSD_ / EW, EW>>>(x);

    // 2) Q,K,V sparse GEMMs (64-row tiles)
    sgemm8<<<dim3(6, 512), 512>>>(0, wq, nullptr, 0, D_, D_);
    sgemm8<<<dim3(6, 512), 512>>>(0, wk, nullptr, 1, D_, D_);
    sgemm8<<<dim3(6, 512), 512>>>(0, wv, nullptr, 2, D_, D_);

    // 3) BN stats (two-pass) for Q, V, K
    k_redA<<<dim3(512, 8), 256>>>(0, SD_); k_finA<<<8, 256>>>(SD_, ST_Q);
    k_redB<<<dim3(512, 8), 256>>>(0, SD_, ST_Q); k_finB<<<8, 256>>>(SD_, ST_Q);
    k_redA<<<dim3(512, 8), 256>>>(2, SD_); k_finA<<<8, 256>>>(SD_, ST_V);
    k_redB<<<dim3(512, 8), 256>>>(2, SD_, ST_V); k_finB<<<8, 256>>>(SD_, ST_V);
    k_redA<<<dim3(512, 8), 256>>>(1, SD_); k_finA<<<8, 256>>>(SD_, ST_K);
    k_redB<<<dim3(512, 8), 256>>>(1, SD_, ST_K); k_finB<<<8, 256>>>(SD_, ST_K);

    // 4) fused BN+IF, membrane carried Q -> V -> K
    k_ifqvk<<<BSD_ / EW, EW>>>();

    // 5) QK (integer) + IF + QKV spike mask (fused pack)
    k_qk<<<dim3(D_ / 256, T_ * B_, 4), 256>>>();
    k_qks<<<BD_ / EW, EW>>>();
    k_qkvm<<<TBSD_ / EW, EW>>>();

    // 6) att = QKV @ wo + BN stats
    sgemm8<<<dim3(6, 512), 512>>>(1, wo, nullptr, 3, D_, D_);
    k_redA<<<dim3(512, 8), 256>>>(3, SD_); k_finA<<<8, 256>>>(SD_, ST_ATT);
    k_redB<<<dim3(512, 8), 256>>>(3, SD_, ST_ATT); k_finB<<<8, 256>>>(SD_, ST_ATT);

    // 7) h = sp + bn(att); sp2 = IF(h) + mask pack (fused)
    k_hsp2<<<BSD_ / EW, EW>>>();

    // 8) o1 = sp2 @ w1 + b1; BN; s1 = IF(bn(o1)) + mask pack (fused)
    sgemm8<<<dim3(24, 512), 512>>>(2, w1, b1, 4, HF_, D_);
    k_redA<<<dim3(512, 8), 256>>>(4, SH_); k_finA<<<8, 256>>>(SH_, ST_O1);
    k_redB<<<dim3(512, 8), 256>>>(4, SH_, ST_O1); k_finB<<<8, 256>>>(SH_, ST_O1);
    k_s1<<<BSH_ / EW, EW>>>();

    // 9) o2 = s1 @ w2 + b2; BN
    sgemm8<<<dim3(6, 512), 512>>>(3, w2, b2, 5, D_, HF_);
    k_redA<<<dim3(512, 8), 256>>>(5, SD_); k_finA<<<8, 256>>>(SD_, ST_O2);
    k_redB<<<dim3(512, 8), 256>>>(5, SD_, ST_O2); k_finB<<<8, 256>>>(SD_, ST_O2);

    // 10) out = h + bn(o2)
    k_out<<<TBSD_ / EW, EW>>>(out);
}

// round 13
// speedup vs baseline: 1.2400x; 1.0337x over previous
#include <cuda_runtime.h>
#include <cstdint>

typedef unsigned long long ULL;
typedef unsigned char u8;
typedef unsigned int u32;

// ---------------- problem dims ----------------
#define T_  4
#define B_  8
#define S_  1024
#define D_  768
#define HF_ 3072
#define SD_   (S_*D_)
#define SH_   (S_*HF_)
#define BSD_  (B_*SD_)
#define BSH_  (B_*SH_)
#define TBSD_ (T_*BSD_)
#define TBSH_ (T_*BSH_)
#define TBD_  (T_*B_*D_)
#define BD_   (B_*D_)
#define MROWS_ (T_*B_*S_)

#define KC_  256   // Eigen gebp k-panel (confirmed R4)
#define KS_  32    // k per GEMM pipeline stage (1 mask word)

// bn-stat stages
#define ST_Q   0
#define ST_V   1
#define ST_K   2
#define ST_ATT 3
#define ST_O1  4
#define ST_O2  5

// ---------------- device scratch ----------------
__device__ u8    g_sp  [TBSD_];
__device__ float g_q   [TBSD_];
__device__ float g_k   [TBSD_];
__device__ float g_v   [TBSD_];
__device__ u8    g_qs  [TBSD_];
__device__ u8    g_ks  [TBSD_];
__device__ u8    g_vs  [TBSD_];
__device__ float g_att [TBSD_];
__device__ float g_h   [TBSD_];
__device__ float g_o1  [TBSH_];
__device__ float g_o2  [TBSD_];
__device__ int   g_qkp [4*TBD_];
__device__ u8    g_qks [TBD_];
__device__ float g_part[8*512];
__device__ float g_mean [6*8];
__device__ float g_denom[6*8];

// bitmasks, TRANSPOSED: [k/32][M] (contiguous in M for cp.async)
__device__ u32 g_msk_sp  [(D_/32)*MROWS_];
__device__ u32 g_msk_qkvm[(D_/32)*MROWS_];
__device__ u32 g_msk_sp2 [(D_/32)*MROWS_];
__device__ u32 g_msk_s1  [(HF_/32)*MROWS_];

// pointer tables (capture-safe: host never queries symbols)
__device__ u32*   g_ptrM[4];
__device__ float* g_ptrF[6];
__global__ void k_init_ptrs() {
    if (threadIdx.x == 0 && blockIdx.x == 0) {
        g_ptrM[0] = g_msk_sp; g_ptrM[1] = g_msk_qkvm; g_ptrM[2] = g_msk_sp2; g_ptrM[3] = g_msk_s1;
        g_ptrF[0] = g_q;   g_ptrF[1] = g_k;    g_ptrF[2] = g_v;
        g_ptrF[3] = g_att; g_ptrF[4] = g_o1;   g_ptrF[5] = g_o2;
    }
}

// ---------------- f32x2 helpers (bitwise 2x IEEE fp32 ops) ----------------
__device__ __forceinline__ ULL add2(ULL a, ULL b) {
    ULL r; asm("add.rn.f32x2 %0, %1, %2;" : "=l"(r) : "l"(a), "l"(b)); return r;
}
__device__ __forceinline__ float2 unpack2(ULL v) {
    float2 r; asm("mov.b64 {%0, %1}, %2;" : "=f"(r.x), "=f"(r.y) : "l"(v)); return r;
}

// ---------------- cp.async helpers ----------------
__device__ __forceinline__ void cp_async16(uint32_t smem, const void* g) {
    asm volatile("cp.async.cg.shared.global [%0], [%1], 16;" :: "r"(smem), "l"(g));
}
__device__ __forceinline__ void cp_commit() {
    asm volatile("cp.async.commit_group;");
}
__device__ __forceinline__ void cp_wait0() {
    asm volatile("cp.async.wait_group 0;");
}

// ---------------- sparse spike GEMM (sgemm9) ----------------
// C[M,N] = spikes(A) @ B[K,N] (+bias), A given as bitmasks MaskT[k/32][M].
// BITWISE identical to the Eigen-emulating dense chain: per output, ascending-k
// FADD of B[k][n] for set bits only; exhausted masks give __ffs(0)=0 -> smem
// row 0 which is permanently zero (+0.0 adds are exact identities). Panels of
// 256 k combined by FADD in ascending order, bias last.
// Tile 64x128, 512 threads: warp = 4 rows (2 pairs), lane = 4 cols.
// 2 blocks/SM (regs capped 64). ONE __syncthreads per stage:
//   wait0 -> sync -> issue copy(s+1)->buf^1 -> compute(buf).
__global__ __launch_bounds__(512, 2)
void sgemm9(int aSel, const float* __restrict__ Bm, const float* __restrict__ bias,
            int cSel, int N, int K)
{
    __shared__ __align__(16) float Bs[2][34][128];  // row 0 = zeros; rows 1..32 = B slab
    __shared__ __align__(16) u32  Msm[2][64];

    const u32* __restrict__ Mt = g_ptrM[aSel];
    float* __restrict__ C = g_ptrF[cSel];

    const int tid  = threadIdx.x;
    const int wid  = tid >> 5;          // 0..15
    const int lane = tid & 31;
    const int bn = blockIdx.x, bm = blockIdx.y;
    const int lane4 = lane * 4;

    // copy mapping: 32 rows x 128 cols per stage -> smem rows 1..32
    const int crow = tid >> 4;          // 0..31
    const int cch  = (tid & 15) * 8;    // float offset, 0..120 step 8 (32B)

    uint32_t sB0 = (uint32_t)__cvta_generic_to_shared(&Bs[0][crow + 1][cch]);
    uint32_t sB1 = (uint32_t)__cvta_generic_to_shared(&Bs[1][crow + 1][cch]);
    uint32_t sM0 = (uint32_t)__cvta_generic_to_shared(&Msm[0][0]);
    uint32_t sM1 = (uint32_t)__cvta_generic_to_shared(&Msm[1][0]);

    // zero dummy row 0 of both stages
    if (tid < 128) { Bs[0][0][tid] = 0.0f; Bs[1][0][tid] = 0.0f; }

    const int S = K / KS_;

    // prologue: copy stage 0
    {
        const float* src = Bm + (size_t)crow * N + bn * 128 + cch;
        cp_async16(sB0, src);
        cp_async16(sB0 + 16, src + 4);
        if (tid < 16)
            cp_async16(sM0 + tid * 16, Mt + bm * 64 + tid * 4);
        cp_commit();
    }

    ULL acc[4][2], part[4][2];
#pragma unroll
    for (int r = 0; r < 4; r++) {
        acc[r][0] = 0ULL; acc[r][1] = 0ULL;
        part[r][0] = 0ULL; part[r][1] = 0ULL;
    }

    for (int s = 0; s < S; s++) {
        const int buf = s & 1;
        cp_wait0();
        __syncthreads();

        // issue next stage's copy into the other buffer (safe: all warps have
        // finished computing on buf^1 by passing the sync above)
        if (s + 1 < S) {
            const int k0 = (s + 1) * KS_;
            const float* src = Bm + (size_t)(k0 + crow) * N + bn * 128 + cch;
            uint32_t dB = buf ? sB0 : sB1;
            cp_async16(dB, src);
            cp_async16(dB + 16, src + 4);
            if (tid < 16)
                cp_async16((buf ? sM0 : sM1) + tid * 16,
                           Mt + (size_t)(s + 1) * MROWS_ + bm * 64 + tid * 4);
            cp_commit();
        }

#pragma unroll
        for (int rp = 0; rp < 2; rp++) {
            u32 w0 = Msm[buf][wid * 4 + 2 * rp];
            u32 w1 = Msm[buf][wid * 4 + 2 * rp + 1];
            int p0c = __popc(w0), p1c = __popc(w1);
            int n = ((p0c > p1c ? p0c : p1c) + 3) >> 2;
            ULL a00 = part[2 * rp][0],     a01 = part[2 * rp][1];
            ULL a10 = part[2 * rp + 1][0], a11 = part[2 * rp + 1][1];
            for (int it = 0; it < n; it++) {
#pragma unroll
                for (int u = 0; u < 4; u++) {
                    int k0 = __ffs(w0); w0 &= w0 - 1;   // 0 -> zero row (+0.0)
                    int k1 = __ffs(w1); w1 &= w1 - 1;
                    ulonglong2 v0 = *(const ulonglong2*)&Bs[buf][k0][lane4];
                    ulonglong2 v1 = *(const ulonglong2*)&Bs[buf][k1][lane4];
                    a00 = add2(a00, v0.x); a01 = add2(a01, v0.y);
                    a10 = add2(a10, v1.x); a11 = add2(a11, v1.y);
                }
            }
            part[2 * rp][0] = a00;     part[2 * rp][1] = a01;
            part[2 * rp + 1][0] = a10; part[2 * rp + 1][1] = a11;
        }

        // Eigen panel boundary (every 256 k): FADD-flush part into acc
        if (((s + 1) & 7) == 0) {
#pragma unroll
            for (int r = 0; r < 4; r++) {
                acc[r][0] = add2(acc[r][0], part[r][0]); part[r][0] = 0ULL;
                acc[r][1] = add2(acc[r][1], part[r][1]); part[r][1] = 0ULL;
            }
        }
    }

    float bb[4];
#pragma unroll
    for (int j = 0; j < 4; j++)
        bb[j] = bias ? bias[bn * 128 + lane4 + j] : 0.0f;

#pragma unroll
    for (int r = 0; r < 4; r++) {
        int row = bm * 64 + wid * 4 + r;
        float2 q0 = unpack2(acc[r][0]), q1 = unpack2(acc[r][1]);
        *(float4*)(C + (size_t)row * N + bn * 128 + lane4) =
            make_float4(q0.x + bb[0], q0.y + bb[1], q1.x + bb[2], q1.y + bb[3]);
    }
}

// ---------------- IF on input x -> sp bytes + fused mask pack ----------------
__global__ void k_ifx(const float* __restrict__ x) {
    int j = blockIdx.x * 256 + threadIdx.x;
    if (j >= BSD_) return;
    int lane = threadIdx.x & 31;
    int row = j / D_;              // b*S + s
    int kw  = (j % D_) >> 5;
    float vm = 0.0f;
#pragma unroll
    for (int t = 0; t < T_; t++) {
        int idx = t * BSD_ + j;
        vm += x[idx];
        float s = (vm >= 1.0f) ? 1.0f : 0.0f;
        u8 sb = (u8)s;
        g_sp[idx] = sb;
        u32 bal = __ballot_sync(0xffffffffu, sb != 0);
        if (lane == 0) g_msk_sp[(size_t)kw * MROWS_ + t * (B_ * S_) + row] = bal;
        vm *= (1.0f - s);
    }
}

// ---------------- BN pass A: per-batch sum -> mean ----------------
// Iteration order identical to the original i-strided loop (bit-exact):
// i = blk*256+tid + n*131072, n = t*(SDv/131072) + j.
__global__ void k_redA(int sel, int SDv) {
    const float* __restrict__ X = g_ptrF[sel];
    int b = blockIdx.y;
    int base = blockIdx.x * 256 + threadIdx.x;
    int J = SDv >> 17;   // SDv / 131072 : 6 (D) or 24 (HF)
    float s = 0.0f;
    for (int t = 0; t < T_; t++) {
        const float* Xb = X + (size_t)(t * B_ + b) * SDv;
        for (int j = 0; j < J; j++)
            s += Xb[base + (j << 17)];
    }
    __shared__ float sh[256];
    int tid = threadIdx.x;
    sh[tid] = s; __syncthreads();
    for (int o = 128; o > 0; o >>= 1) { if (tid < o) sh[tid] += sh[tid + o]; __syncthreads(); }
    if (tid == 0) g_part[b * 512 + blockIdx.x] = sh[0];
}

__global__ void k_finA(int SDv, int stage) {
    int b = blockIdx.x, tid = threadIdx.x;
    double s = (double)g_part[b * 512 + tid] + (double)g_part[b * 512 + tid + 256];
    __shared__ double sh[256];
    sh[tid] = s; __syncthreads();
    for (int o = 128; o > 0; o >>= 1) { if (tid < o) sh[tid] += sh[tid + o]; __syncthreads(); }
    if (tid == 0) {
        float E = (float)(T_ * SDv);
        g_mean[stage * 8 + b] = __fdiv_rn((float)sh[0], E);
    }
}

// ---------------- BN pass B: per-batch sum of (x-m)^2 -> denom ----------------
__global__ void k_redB(int sel, int SDv, int stage) {
    const float* __restrict__ X = g_ptrF[sel];
    int b = blockIdx.y;
    float m = g_mean[stage * 8 + b];
    int base = blockIdx.x * 256 + threadIdx.x;
    int J = SDv >> 17;
    float s = 0.0f;
    for (int t = 0; t < T_; t++) {
        const float* Xb = X + (size_t)(t * B_ + b) * SDv;
        for (int j = 0; j < J; j++) {
            float v = Xb[base + (j << 17)] - m;
            s += v * v;
        }
    }
    __shared__ float sh[256];
    int tid = threadIdx.x;
    sh[tid] = s; __syncthreads();
    for (int o = 128; o > 0; o >>= 1) { if (tid < o) sh[tid] += sh[tid + o]; __syncthreads(); }
    if (tid == 0) g_part[b * 512 + blockIdx.x] = sh[0];
}

__global__ void k_finB(int SDv, int stage) {
    int b = blockIdx.x, tid = threadIdx.x;
    double s = (double)g_part[b * 512 + tid] + (double)g_part[b * 512 + tid + 256];
    __shared__ double sh[256];
    sh[tid] = s; __syncthreads();
    for (int o = 128; o > 0; o >>= 1) { if (tid < o) sh[tid] += sh[tid + o]; __syncthreads(); }
    if (tid == 0) {
        float E = (float)(T_ * SDv);
        float var_f = __fdiv_rn((float)sh[0], E);
        g_denom[stage * 8 + b] = __fsqrt_rn(var_f + 1e-5f);
    }
}

// ---------------- fused BN + IF over Q,V,K with CARRIED membrane ----------------
__global__ void k_ifqvk() {
    int j = blockIdx.x * 256 + threadIdx.x;
    if (j >= BSD_) return;
    int b = j / SD_;
    float mq = g_mean[ST_Q * 8 + b], dq = g_denom[ST_Q * 8 + b];
    float mv = g_mean[ST_V * 8 + b], dv = g_denom[ST_V * 8 + b];
    float mk = g_mean[ST_K * 8 + b], dk = g_denom[ST_K * 8 + b];
    float vm = 0.0f;
#pragma unroll
    for (int t = 0; t < T_; t++) {
        int idx = t * BSD_ + j;
        vm += __fdiv_rn(g_q[idx] - mq, dq);
        float s = (vm >= 1.0f) ? 1.0f : 0.0f;
        g_qs[idx] = (u8)s;
        vm *= (1.0f - s);
    }
#pragma unroll
    for (int t = 0; t < T_; t++) {
        int idx = t * BSD_ + j;
        vm += __fdiv_rn(g_v[idx] - mv, dv);
        float s = (vm >= 1.0f) ? 1.0f : 0.0f;
        g_vs[idx] = (u8)s;
        vm *= (1.0f - s);
    }
#pragma unroll
    for (int t = 0; t < T_; t++) {
        int idx = t * BSD_ + j;
        vm += __fdiv_rn(g_k[idx] - mk, dk);
        float s = (vm >= 1.0f) ? 1.0f : 0.0f;
        g_ks[idx] = (u8)s;
        vm *= (1.0f - s);
    }
}

// ---------------- QK: integer seq-reduction (exact) ----------------
__global__ void k_qk() {
    int d = blockIdx.x * 256 + threadIdx.x;
    int tb = blockIdx.y;
    int sp = blockIdx.z;
    int acc = 0;
    int s0 = sp * 256;
    for (int s = s0; s < s0 + 256; s++) {
        size_t idx = ((size_t)tb * S_ + s) * D_ + d;
        acc += (int)(g_qs[idx] & g_ks[idx]);
    }
    g_qkp[sp * TBD_ + tb * D_ + d] = acc;
}

// QKs = IF(QK) over t (integers exact in fp32)
__global__ void k_qks() {
    int i = blockIdx.x * 256 + threadIdx.x;
    if (i >= BD_) return;
    int b = i / D_, d = i - b * D_;
    float vm = 0.0f;
#pragma unroll
    for (int t = 0; t < T_; t++) {
        int idx = (t * B_ + b) * D_ + d;
        int qk = g_qkp[idx] + g_qkp[TBD_ + idx] + g_qkp[2 * TBD_ + idx] +
                 g_qkp[3 * TBD_ + idx];
        vm += (float)qk;
        float s = (vm >= 1.0f) ? 1.0f : 0.0f;
        g_qks[idx] = (u8)s;
        vm *= (1.0f - s);
    }
}

// QKV spikes = Vs & QKs, mask emitted directly
__global__ void k_qkvm() {
    int idx = blockIdx.x * 256 + threadIdx.x;
    if (idx >= TBSD_) return;
    int lane = threadIdx.x & 31;
    int d = idx % D_;
    int tb = idx / SD_;           // t*B + b
    u8 v = g_vs[idx] & g_qks[tb * D_ + d];
    u32 bal = __ballot_sync(0xffffffffu, v != 0);
    if (lane == 0) {
        int m = idx / D_;         // == t*B*S + b*S + s
        int kw = d >> 5;
        g_msk_qkvm[(size_t)kw * MROWS_ + m] = bal;
    }
}

// h = sp + bn(att); sp2 = IF(h), mask emitted directly
__global__ void k_hsp2() {
    int j = blockIdx.x * 256 + threadIdx.x;
    if (j >= BSD_) return;
    int lane = threadIdx.x & 31;
    int b = j / SD_;
    int row = j / D_;
    int kw = (j % D_) >> 5;
    float m = g_mean[ST_ATT * 8 + b], dn = g_denom[ST_ATT * 8 + b];
    float vm = 0.0f;
#pragma unroll
    for (int t = 0; t < T_; t++) {
        int idx = t * BSD_ + j;
        float hval = (float)g_sp[idx] + __fdiv_rn(g_att[idx] - m, dn);
        g_h[idx] = hval;
        vm += hval;
        float s = (vm >= 1.0f) ? 1.0f : 0.0f;
        u32 bal = __ballot_sync(0xffffffffu, s != 0.0f);
        if (lane == 0) g_msk_sp2[(size_t)kw * MROWS_ + t * (B_ * S_) + row] = bal;
        vm *= (1.0f - s);
    }
}

// s1 = IF(bn(o1)), mask emitted directly
__global__ void k_s1() {
    int j = blockIdx.x * 256 + threadIdx.x;
    if (j >= BSH_) return;
    int lane = threadIdx.x & 31;
    int b = j / SH_;
    int row = j / HF_;
    int kw = (j % HF_) >> 5;
    float m = g_mean[ST_O1 * 8 + b], dn = g_denom[ST_O1 * 8 + b];
    float vm = 0.0f;
#pragma unroll
    for (int t = 0; t < T_; t++) {
        int idx = t * BSH_ + j;
        vm += __fdiv_rn(g_o1[idx] - m, dn);
        float s = (vm >= 1.0f) ? 1.0f : 0.0f;
        u32 bal = __ballot_sync(0xffffffffu, s != 0.0f);
        if (lane == 0) g_msk_s1[(size_t)kw * MROWS_ + t * (B_ * S_) + row] = bal;
        vm *= (1.0f - s);
    }
}

// out = h + bn(o2), float4
__global__ void k_out(float* __restrict__ out) {
    int idx4 = blockIdx.x * 256 + threadIdx.x;
    if (idx4 >= TBSD_ / 4) return;
    int idx = idx4 * 4;
    int b = (idx / SD_) % B_;
    float m = g_mean[ST_O2 * 8 + b], dn = g_denom[ST_O2 * 8 + b];
    float4 hv = *(const float4*)(g_h + idx);
    float4 ov = *(const float4*)(g_o2 + idx);
    float4 r;
    r.x = hv.x + __fdiv_rn(ov.x - m, dn);
    r.y = hv.y + __fdiv_rn(ov.y - m, dn);
    r.z = hv.z + __fdiv_rn(ov.z - m, dn);
    r.w = hv.w + __fdiv_rn(ov.w - m, dn);
    *(float4*)(out + idx) = r;
}

// ---------------- launch (kernel launches ONLY — capture-safe) ----------------
extern "C" void kernel_launch(void* const* d_in, const int* in_sizes, int n_in,
                              void* d_out, int out_size) {
    (void)in_sizes; (void)n_in; (void)out_size;
    const float* x  = (const float*)d_in[0];
    const float* wq = (const float*)d_in[1];
    const float* wk = (const float*)d_in[2];
    const float* wv = (const float*)d_in[3];
    const float* wo = (const float*)d_in[4];
    const float* w1 = (const float*)d_in[5];
    const float* b1 = (const float*)d_in[6];
    const float* w2 = (const float*)d_in[7];
    const float* b2 = (const float*)d_in[8];
    float* out = (float*)d_out;

    const int EW = 256;
    k_init_ptrs<<<1, 32>>>();

    // 1) sp = IF(x) + mask pack (fused)
    k_ifx<<<BSD_ / EW, EW>>>(x);

    // 2) Q,K,V sparse GEMMs (64-row tiles)
    sgemm9<<<dim3(6, 512), 512>>>(0, wq, nullptr, 0, D_, D_);
    sgemm9<<<dim3(6, 512), 512>>>(0, wk, nullptr, 1, D_, D_);
    sgemm9<<<dim3(6, 512), 512>>>(0, wv, nullptr, 2, D_, D_);

    // 3) BN stats (two-pass) for Q, V, K
    k_redA<<<dim3(512, 8), 256>>>(0, SD_); k_finA<<<8, 256>>>(SD_, ST_Q);
    k_redB<<<dim3(512, 8), 256>>>(0, SD_, ST_Q); k_finB<<<8, 256>>>(SD_, ST_Q);
    k_redA<<<dim3(512, 8), 256>>>(2, SD_); k_finA<<<8, 256>>>(SD_, ST_V);
    k_redB<<<dim3(512, 8), 256>>>(2, SD_, ST_V); k_finB<<<8, 256>>>(SD_, ST_V);
    k_redA<<<dim3(512, 8), 256>>>(1, SD_); k_finA<<<8, 256>>>(SD_, ST_K);
    k_redB<<<dim3(512, 8), 256>>>(1, SD_, ST_K); k_finB<<<8, 256>>>(SD_, ST_K);

    // 4) fused BN+IF, membrane carried Q -> V -> K
    k_ifqvk<<<BSD_ / EW, EW>>>();

    // 5) QK (integer) + IF + QKV spike mask (fused pack)
    k_qk<<<dim3(D_ / 256, T_ * B_, 4), 256>>>();
    k_qks<<<BD_ / EW, EW>>>();
    k_qkvm<<<TBSD_ / EW, EW>>>();

    // 6) att = QKV @ wo + BN stats
    sgemm9<<<dim3(6, 512), 512>>>(1, wo, nullptr, 3, D_, D_);
    k_redA<<<dim3(512, 8), 256>>>(3, SD_); k_finA<<<8, 256>>>(SD_, ST_ATT);
    k_redB<<<dim3(512, 8), 256>>>(3, SD_, ST_ATT); k_finB<<<8, 256>>>(SD_, ST_ATT);

    // 7) h = sp + bn(att); sp2 = IF(h) + mask pack (fused)
    k_hsp2<<<BSD_ / EW, EW>>>();

    // 8) o1 = sp2 @ w1 + b1; BN; s1 = IF(bn(o1)) + mask pack (fused)
    sgemm9<<<dim3(24, 512), 512>>>(2, w1, b1, 4, HF_, D_);
    k_redA<<<dim3(512, 8), 256>>>(4, SH_); k_finA<<<8, 256>>>(SH_, ST_O1);
    k_redB<<<dim3(512, 8), 256>>>(4, SH_, ST_O1); k_finB<<<8, 256>>>(SH_, ST_O1);
    k_s1<<<BSH_ / EW, EW>>>();

    // 9) o2 = s1 @ w2 + b2; BN
    sgemm9<<<dim3(6, 512), 512>>>(3, w2, b2, 5, D_, HF_);
    k_redA<<<dim3(512, 8), 256>>>(5, SD_); k_finA<<<8, 256>>>(SD_, ST_O2);
    k_redB<<<dim3(512, 8), 256>>>(5, SD_, ST_O2); k_finB<<<8, 256>>>(SD_, ST_O2);

    // 10) out = h + bn(o2)
    k_out<<<TBSD_ / (EW * 4), EW>>>(out);
}

// round 14
// speedup vs baseline: 1.4719x; 1.1870x over previous
#include <cuda_runtime.h>
#include <cstdint>

typedef unsigned long long ULL;
typedef unsigned char u8;
typedef unsigned int u32;

// ---------------- problem dims ----------------
#define T_  4
#define B_  8
#define S_  1024
#define D_  768
#define HF_ 3072
#define SD_   (S_*D_)
#define SH_   (S_*HF_)
#define BSD_  (B_*SD_)
#define BSH_  (B_*SH_)
#define TBSD_ (T_*BSD_)
#define TBSH_ (T_*BSH_)
#define TBD_  (T_*B_*D_)
#define BD_   (B_*D_)
#define MROWS_ (T_*B_*S_)

#define KC_  256   // Eigen gebp k-panel (confirmed R4)
#define KS_  32    // k per GEMM pipeline stage (1 mask word)

// bn-stat stages
#define ST_Q   0
#define ST_V   1
#define ST_K   2
#define ST_ATT 3
#define ST_O1  4
#define ST_O2  5

// ---------------- device scratch ----------------
__device__ u8    g_sp  [TBSD_];
__device__ float g_q   [TBSD_];
__device__ float g_k   [TBSD_];
__device__ float g_v   [TBSD_];
__device__ u8    g_qs  [TBSD_];
__device__ u8    g_ks  [TBSD_];
__device__ u8    g_vs  [TBSD_];
__device__ float g_att [TBSD_];
__device__ float g_h   [TBSD_];
__device__ float g_o1  [TBSH_];
__device__ float g_o2  [TBSD_];
__device__ int   g_qkp [4*TBD_];
__device__ u8    g_qks [TBD_];
__device__ float g_part[8*512];
__device__ float g_mean [6*8];
__device__ float g_denom[6*8];

// bitmasks, TRANSPOSED: [k/32][M] (contiguous in M for cp.async)
__device__ u32 g_msk_sp  [(D_/32)*MROWS_];
__device__ u32 g_msk_qkvm[(D_/32)*MROWS_];
__device__ u32 g_msk_sp2 [(D_/32)*MROWS_];
__device__ u32 g_msk_s1  [(HF_/32)*MROWS_];

// pointer tables (capture-safe: host never queries symbols)
__device__ u32*   g_ptrM[4];
__device__ float* g_ptrF[6];
__global__ void k_init_ptrs() {
    if (threadIdx.x == 0 && blockIdx.x == 0) {
        g_ptrM[0] = g_msk_sp; g_ptrM[1] = g_msk_qkvm; g_ptrM[2] = g_msk_sp2; g_ptrM[3] = g_msk_s1;
        g_ptrF[0] = g_q;   g_ptrF[1] = g_k;    g_ptrF[2] = g_v;
        g_ptrF[3] = g_att; g_ptrF[4] = g_o1;   g_ptrF[5] = g_o2;
    }
}

// ---------------- f32x2 helpers (bitwise 2x IEEE fp32 ops) ----------------
__device__ __forceinline__ ULL add2(ULL a, ULL b) {
    ULL r; asm("add.rn.f32x2 %0, %1, %2;" : "=l"(r) : "l"(a), "l"(b)); return r;
}
__device__ __forceinline__ float2 unpack2(ULL v) {
    float2 r; asm("mov.b64 {%0, %1}, %2;" : "=f"(r.x), "=f"(r.y) : "l"(v)); return r;
}

// ---------------- cp.async helpers ----------------
__device__ __forceinline__ void cp_async16(uint32_t smem, const void* g) {
    asm volatile("cp.async.cg.shared.global [%0], [%1], 16;" :: "r"(smem), "l"(g));
}
__device__ __forceinline__ void cp_commit() {
    asm volatile("cp.async.commit_group;");
}
__device__ __forceinline__ void cp_wait0() {
    asm volatile("cp.async.wait_group 0;");
}

// ---------------- sparse spike GEMM (sgemm10) ----------------
// C[M,N] = spikes(A) @ B[K,N] (+bias), A given as bitmasks MaskT[k/32][M].
// BITWISE identical to the Eigen-emulating dense chain: per output, ascending-k
// FADD of B[k][n] for set bits only; when a row's mask is exhausted __ffs(0)=0
// -> smem row 0 which is permanently zero (+0.0 adds are exact identities).
// Panels of 256 k combined by FADD in ascending order, bias last.
// Tile 64x128, 512 threads: warp = 4 rows (2 pairs), lane = 4 cols.
// 2 blocks/SM (regs capped 64). ONE __syncthreads per stage.
// EXACT while-loop per pair (no ceil-4 padding): slots = 2*max(popc) instead of
// 8*ceil(max/4), cutting ~15-30% dummy crossbar traffic.
__global__ __launch_bounds__(512, 2)
void sgemm10(int aSel, const float* __restrict__ Bm, const float* __restrict__ bias,
             int cSel, int N, int K)
{
    __shared__ __align__(16) float Bs[2][34][128];  // row 0 = zeros; rows 1..32 = B slab
    __shared__ __align__(16) u32  Msm[2][64];

    const u32* __restrict__ Mt = g_ptrM[aSel];
    float* __restrict__ C = g_ptrF[cSel];

    const int tid  = threadIdx.x;
    const int wid  = tid >> 5;          // 0..15
    const int lane = tid & 31;
    const int bn = blockIdx.x, bm = blockIdx.y;
    const int lane4 = lane * 4;

    // copy mapping: 32 rows x 128 cols per stage -> smem rows 1..32
    const int crow = tid >> 4;          // 0..31
    const int cch  = (tid & 15) * 8;    // float offset, 0..120 step 8 (32B)

    uint32_t sB0 = (uint32_t)__cvta_generic_to_shared(&Bs[0][crow + 1][cch]);
    uint32_t sB1 = (uint32_t)__cvta_generic_to_shared(&Bs[1][crow + 1][cch]);
    uint32_t sM0 = (uint32_t)__cvta_generic_to_shared(&Msm[0][0]);
    uint32_t sM1 = (uint32_t)__cvta_generic_to_shared(&Msm[1][0]);

    // zero dummy row 0 of both stages
    if (tid < 128) { Bs[0][0][tid] = 0.0f; Bs[1][0][tid] = 0.0f; }

    const int S = K / KS_;

    // prologue: copy stage 0
    {
        const float* src = Bm + (size_t)crow * N + bn * 128 + cch;
        cp_async16(sB0, src);
        cp_async16(sB0 + 16, src + 4);
        if (tid < 16)
            cp_async16(sM0 + tid * 16, Mt + bm * 64 + tid * 4);
        cp_commit();
    }

    ULL acc[4][2], part[4][2];
#pragma unroll
    for (int r = 0; r < 4; r++) {
        acc[r][0] = 0ULL; acc[r][1] = 0ULL;
        part[r][0] = 0ULL; part[r][1] = 0ULL;
    }

    for (int s = 0; s < S; s++) {
        const int buf = s & 1;
        cp_wait0();
        __syncthreads();

        // issue next stage's copy into the other buffer (safe: all warps have
        // finished computing on buf^1 by passing the sync above)
        if (s + 1 < S) {
            const int k0 = (s + 1) * KS_;
            const float* src = Bm + (size_t)(k0 + crow) * N + bn * 128 + cch;
            uint32_t dB = buf ? sB0 : sB1;
            cp_async16(dB, src);
            cp_async16(dB + 16, src + 4);
            if (tid < 16)
                cp_async16((buf ? sM0 : sM1) + tid * 16,
                           Mt + (size_t)(s + 1) * MROWS_ + bm * 64 + tid * 4);
            cp_commit();
        }

#pragma unroll
        for (int rp = 0; rp < 2; rp++) {
            u32 w0 = Msm[buf][wid * 4 + 2 * rp];
            u32 w1 = Msm[buf][wid * 4 + 2 * rp + 1];
            ULL a00 = part[2 * rp][0],     a01 = part[2 * rp][1];
            ULL a10 = part[2 * rp + 1][0], a11 = part[2 * rp + 1][1];
            while (w0 | w1) {
                int k0 = __ffs(w0); w0 &= w0 - 1;   // 0 -> zero row (+0.0)
                int k1 = __ffs(w1); w1 &= w1 - 1;
                ulonglong2 v0 = *(const ulonglong2*)&Bs[buf][k0][lane4];
                ulonglong2 v1 = *(const ulonglong2*)&Bs[buf][k1][lane4];
                a00 = add2(a00, v0.x); a01 = add2(a01, v0.y);
                a10 = add2(a10, v1.x); a11 = add2(a11, v1.y);
            }
            part[2 * rp][0] = a00;     part[2 * rp][1] = a01;
            part[2 * rp + 1][0] = a10; part[2 * rp + 1][1] = a11;
        }

        // Eigen panel boundary (every 256 k): FADD-flush part into acc
        if (((s + 1) & 7) == 0) {
#pragma unroll
            for (int r = 0; r < 4; r++) {
                acc[r][0] = add2(acc[r][0], part[r][0]); part[r][0] = 0ULL;
                acc[r][1] = add2(acc[r][1], part[r][1]); part[r][1] = 0ULL;
            }
        }
    }

    float bb[4];
#pragma unroll
    for (int j = 0; j < 4; j++)
        bb[j] = bias ? bias[bn * 128 + lane4 + j] : 0.0f;

#pragma unroll
    for (int r = 0; r < 4; r++) {
        int row = bm * 64 + wid * 4 + r;
        float2 q0 = unpack2(acc[r][0]), q1 = unpack2(acc[r][1]);
        *(float4*)(C + (size_t)row * N + bn * 128 + lane4) =
            make_float4(q0.x + bb[0], q0.y + bb[1], q1.x + bb[2], q1.y + bb[3]);
    }
}

// ---------------- IF on input x -> sp bytes + fused mask pack ----------------
__global__ void k_ifx(const float* __restrict__ x) {
    int j = blockIdx.x * 256 + threadIdx.x;
    if (j >= BSD_) return;
    int lane = threadIdx.x & 31;
    int row = j / D_;              // b*S + s
    int kw  = (j % D_) >> 5;
    float vm = 0.0f;
#pragma unroll
    for (int t = 0; t < T_; t++) {
        int idx = t * BSD_ + j;
        vm += x[idx];
        float s = (vm >= 1.0f) ? 1.0f : 0.0f;
        u8 sb = (u8)s;
        g_sp[idx] = sb;
        u32 bal = __ballot_sync(0xffffffffu, sb != 0);
        if (lane == 0) g_msk_sp[(size_t)kw * MROWS_ + t * (B_ * S_) + row] = bal;
        vm *= (1.0f - s);
    }
}

// ---------------- BN pass A: per-batch sum -> mean ----------------
// Iteration order identical to the original i-strided loop (bit-exact).
__global__ void k_redA(int sel, int SDv) {
    const float* __restrict__ X = g_ptrF[sel];
    int b = blockIdx.y;
    int base = blockIdx.x * 256 + threadIdx.x;
    int J = SDv >> 17;   // SDv / 131072 : 6 (D) or 24 (HF)
    float s = 0.0f;
    for (int t = 0; t < T_; t++) {
        const float* Xb = X + (size_t)(t * B_ + b) * SDv;
        for (int j = 0; j < J; j++)
            s += Xb[base + (j << 17)];
    }
    __shared__ float sh[256];
    int tid = threadIdx.x;
    sh[tid] = s; __syncthreads();
    for (int o = 128; o > 0; o >>= 1) { if (tid < o) sh[tid] += sh[tid + o]; __syncthreads(); }
    if (tid == 0) g_part[b * 512 + blockIdx.x] = sh[0];
}

__global__ void k_finA(int SDv, int stage) {
    int b = blockIdx.x, tid = threadIdx.x;
    double s = (double)g_part[b * 512 + tid] + (double)g_part[b * 512 + tid + 256];
    __shared__ double sh[256];
    sh[tid] = s; __syncthreads();
    for (int o = 128; o > 0; o >>= 1) { if (tid < o) sh[tid] += sh[tid + o]; __syncthreads(); }
    if (tid == 0) {
        float E = (float)(T_ * SDv);
        g_mean[stage * 8 + b] = __fdiv_rn((float)sh[0], E);
    }
}

// ---------------- BN pass B: per-batch sum of (x-m)^2 -> denom ----------------
__global__ void k_redB(int sel, int SDv, int stage) {
    const float* __restrict__ X = g_ptrF[sel];
    int b = blockIdx.y;
    float m = g_mean[stage * 8 + b];
    int base = blockIdx.x * 256 + threadIdx.x;
    int J = SDv >> 17;
    float s = 0.0f;
    for (int t = 0; t < T_; t++) {
        const float* Xb = X + (size_t)(t * B_ + b) * SDv;
        for (int j = 0; j < J; j++) {
            float v = Xb[base + (j << 17)] - m;
            s += v * v;
        }
    }
    __shared__ float sh[256];
    int tid = threadIdx.x;
    sh[tid] = s; __syncthreads();
    for (int o = 128; o > 0; o >>= 1) { if (tid < o) sh[tid] += sh[tid + o]; __syncthreads(); }
    if (tid == 0) g_part[b * 512 + blockIdx.x] = sh[0];
}

__global__ void k_finB(int SDv, int stage) {
    int b = blockIdx.x, tid = threadIdx.x;
    double s = (double)g_part[b * 512 + tid] + (double)g_part[b * 512 + tid + 256];
    __shared__ double sh[256];
    sh[tid] = s; __syncthreads();
    for (int o = 128; o > 0; o >>= 1) { if (tid < o) sh[tid] += sh[tid + o]; __syncthreads(); }
    if (tid == 0) {
        float E = (float)(T_ * SDv);
        float var_f = __fdiv_rn((float)sh[0], E);
        g_denom[stage * 8 + b] = __fsqrt_rn(var_f + 1e-5f);
    }
}

// ---------------- fused BN + IF over Q,V,K with CARRIED membrane ----------------
__global__ void k_ifqvk() {
    int j = blockIdx.x * 256 + threadIdx.x;
    if (j >= BSD_) return;
    int b = j / SD_;
    float mq = g_mean[ST_Q * 8 + b], dq = g_denom[ST_Q * 8 + b];
    float mv = g_mean[ST_V * 8 + b], dv = g_denom[ST_V * 8 + b];
    float mk = g_mean[ST_K * 8 + b], dk = g_denom[ST_K * 8 + b];
    float vm = 0.0f;
#pragma unroll
    for (int t = 0; t < T_; t++) {
        int idx = t * BSD_ + j;
        vm += __fdiv_rn(g_q[idx] - mq, dq);
        float s = (vm >= 1.0f) ? 1.0f : 0.0f;
        g_qs[idx] = (u8)s;
        vm *= (1.0f - s);
    }
#pragma unroll
    for (int t = 0; t < T_; t++) {
        int idx = t * BSD_ + j;
        vm += __fdiv_rn(g_v[idx] - mv, dv);
        float s = (vm >= 1.0f) ? 1.0f : 0.0f;
        g_vs[idx] = (u8)s;
        vm *= (1.0f - s);
    }
#pragma unroll
    for (int t = 0; t < T_; t++) {
        int idx = t * BSD_ + j;
        vm += __fdiv_rn(g_k[idx] - mk, dk);
        float s = (vm >= 1.0f) ? 1.0f : 0.0f;
        g_ks[idx] = (u8)s;
        vm *= (1.0f - s);
    }
}

// ---------------- QK: integer seq-reduction (exact) ----------------
__global__ void k_qk() {
    int d = blockIdx.x * 256 + threadIdx.x;
    int tb = blockIdx.y;
    int sp = blockIdx.z;
    int acc = 0;
    int s0 = sp * 256;
    for (int s = s0; s < s0 + 256; s++) {
        size_t idx = ((size_t)tb * S_ + s) * D_ + d;
        acc += (int)(g_qs[idx] & g_ks[idx]);
    }
    g_qkp[sp * TBD_ + tb * D_ + d] = acc;
}

// QKs = IF(QK) over t (integers exact in fp32)
__global__ void k_qks() {
    int i = blockIdx.x * 256 + threadIdx.x;
    if (i >= BD_) return;
    int b = i / D_, d = i - b * D_;
    float vm = 0.0f;
#pragma unroll
    for (int t = 0; t < T_; t++) {
        int idx = (t * B_ + b) * D_ + d;
        int qk = g_qkp[idx] + g_qkp[TBD_ + idx] + g_qkp[2 * TBD_ + idx] +
                 g_qkp[3 * TBD_ + idx];
        vm += (float)qk;
        float s = (vm >= 1.0f) ? 1.0f : 0.0f;
        g_qks[idx] = (u8)s;
        vm *= (1.0f - s);
    }
}

// QKV spikes = Vs & QKs, mask emitted directly
__global__ void k_qkvm() {
    int idx = blockIdx.x * 256 + threadIdx.x;
    if (idx >= TBSD_) return;
    int lane = threadIdx.x & 31;
    int d = idx % D_;
    int tb = idx / SD_;           // t*B + b
    u8 v = g_vs[idx] & g_qks[tb * D_ + d];
    u32 bal = __ballot_sync(0xffffffffu, v != 0);
    if (lane == 0) {
        int m = idx / D_;         // == t*B*S + b*S + s
        int kw = d >> 5;
        g_msk_qkvm[(size_t)kw * MROWS_ + m] = bal;
    }
}

// h = sp + bn(att); sp2 = IF(h), mask emitted directly
__global__ void k_hsp2() {
    int j = blockIdx.x * 256 + threadIdx.x;
    if (j >= BSD_) return;
    int lane = threadIdx.x & 31;
    int b = j / SD_;
    int row = j / D_;
    int kw = (j % D_) >> 5;
    float m = g_mean[ST_ATT * 8 + b], dn = g_denom[ST_ATT * 8 + b];
    float vm = 0.0f;
#pragma unroll
    for (int t = 0; t < T_; t++) {
        int idx = t * BSD_ + j;
        float hval = (float)g_sp[idx] + __fdiv_rn(g_att[idx] - m, dn);
        g_h[idx] = hval;
        vm += hval;
        float s = (vm >= 1.0f) ? 1.0f : 0.0f;
        u32 bal = __ballot_sync(0xffffffffu, s != 0.0f);
        if (lane == 0) g_msk_sp2[(size_t)kw * MROWS_ + t * (B_ * S_) + row] = bal;
        vm *= (1.0f - s);
    }
}

// s1 = IF(bn(o1)), mask emitted directly
__global__ void k_s1() {
    int j = blockIdx.x * 256 + threadIdx.x;
    if (j >= BSH_) return;
    int lane = threadIdx.x & 31;
    int b = j / SH_;
    int row = j / HF_;
    int kw = (j % HF_) >> 5;
    float m = g_mean[ST_O1 * 8 + b], dn = g_denom[ST_O1 * 8 + b];
    float vm = 0.0f;
#pragma unroll
    for (int t = 0; t < T_; t++) {
        int idx = t * BSH_ + j;
        vm += __fdiv_rn(g_o1[idx] - m, dn);
        float s = (vm >= 1.0f) ? 1.0f : 0.0f;
        u32 bal = __ballot_sync(0xffffffffu, s != 0.0f);
        if (lane == 0) g_msk_s1[(size_t)kw * MROWS_ + t * (B_ * S_) + row] = bal;
        vm *= (1.0f - s);
    }
}

// out = h + bn(o2), float4
__global__ void k_out(float* __restrict__ out) {
    int idx4 = blockIdx.x * 256 + threadIdx.x;
    if (idx4 >= TBSD_ / 4) return;
    int idx = idx4 * 4;
    int b = (idx / SD_) % B_;
    float m = g_mean[ST_O2 * 8 + b], dn = g_denom[ST_O2 * 8 + b];
    float4 hv = *(const float4*)(g_h + idx);
    float4 ov = *(const float4*)(g_o2 + idx);
    float4 r;
    r.x = hv.x + __fdiv_rn(ov.x - m, dn);
    r.y = hv.y + __fdiv_rn(ov.y - m, dn);
    r.z = hv.z + __fdiv_rn(ov.z - m, dn);
    r.w = hv.w + __fdiv_rn(ov.w - m, dn);
    *(float4*)(out + idx) = r;
}

// ---------------- launch (kernel launches ONLY — capture-safe) ----------------
extern "C" void kernel_launch(void* const* d_in, const int* in_sizes, int n_in,
                              void* d_out, int out_size) {
    (void)in_sizes; (void)n_in; (void)out_size;
    const float* x  = (const float*)d_in[0];
    const float* wq = (const float*)d_in[1];
    const float* wk = (const float*)d_in[2];
    const float* wv = (const float*)d_in[3];
    const float* wo = (const float*)d_in[4];
    const float* w1 = (const float*)d_in[5];
    const float* b1 = (const float*)d_in[6];
    const float* w2 = (const float*)d_in[7];
    const float* b2 = (const float*)d_in[8];
    float* out = (float*)d_out;

    const int EW = 256;
    k_init_ptrs<<<1, 32>>>();

    // 1) sp = IF(x) + mask pack (fused)
    k_ifx<<<BSD_ / EW, EW>>>(x);

    // 2) Q,K,V sparse GEMMs (64-row tiles)
    sgemm10<<<dim3(6, 512), 512>>>(0, wq, nullptr, 0, D_, D_);
    sgemm10<<<dim3(6, 512), 512>>>(0, wk, nullptr, 1, D_, D_);
    sgemm10<<<dim3(6, 512), 512>>>(0, wv, nullptr, 2, D_, D_);

    // 3) BN stats (two-pass) for Q, V, K
    k_redA<<<dim3(512, 8), 256>>>(0, SD_); k_finA<<<8, 256>>>(SD_, ST_Q);
    k_redB<<<dim3(512, 8), 256>>>(0, SD_, ST_Q); k_finB<<<8, 256>>>(SD_, ST_Q);
    k_redA<<<dim3(512, 8), 256>>>(2, SD_); k_finA<<<8, 256>>>(SD_, ST_V);
    k_redB<<<dim3(512, 8), 256>>>(2, SD_, ST_V); k_finB<<<8, 256>>>(SD_, ST_V);
    k_redA<<<dim3(512, 8), 256>>>(1, SD_); k_finA<<<8, 256>>>(SD_, ST_K);
    k_redB<<<dim3(512, 8), 256>>>(1, SD_, ST_K); k_finB<<<8, 256>>>(SD_, ST_K);

    // 4) fused BN+IF, membrane carried Q -> V -> K
    k_ifqvk<<<BSD_ / EW, EW>>>();

    // 5) QK (integer) + IF + QKV spike mask (fused pack)
    k_qk<<<dim3(D_ / 256, T_ * B_, 4), 256>>>();
    k_qks<<<BD_ / EW, EW>>>();
    k_qkvm<<<TBSD_ / EW, EW>>>();

    // 6) att = QKV @ wo + BN stats
    sgemm10<<<dim3(6, 512), 512>>>(1, wo, nullptr, 3, D_, D_);
    k_redA<<<dim3(512, 8), 256>>>(3, SD_); k_finA<<<8, 256>>>(SD_, ST_ATT);
    k_redB<<<dim3(512, 8), 256>>>(3, SD_, ST_ATT); k_finB<<<8, 256>>>(SD_, ST_ATT);

    // 7) h = sp + bn(att); sp2 = IF(h) + mask pack (fused)
    k_hsp2<<<BSD_ / EW, EW>>>();

    // 8) o1 = sp2 @ w1 + b1; BN; s1 = IF(bn(o1)) + mask pack (fused)
    sgemm10<<<dim3(24, 512), 512>>>(2, w1, b1, 4, HF_, D_);
    k_redA<<<dim3(512, 8), 256>>>(4, SH_); k_finA<<<8, 256>>>(SH_, ST_O1);
    k_redB<<<dim3(512, 8), 256>>>(4, SH_, ST_O1); k_finB<<<8, 256>>>(SH_, ST_O1);
    k_s1<<<BSH_ / EW, EW>>>();

    // 9) o2 = s1 @ w2 + b2; BN
    sgemm10<<<dim3(6, 512), 512>>>(3, w2, b2, 5, D_, HF_);
    k_redA<<<dim3(512, 8), 256>>>(5, SD_); k_finA<<<8, 256>>>(SD_, ST_O2);
    k_redB<<<dim3(512, 8), 256>>>(5, SD_, ST_O2); k_finB<<<8, 256>>>(SD_, ST_O2);

    // 10) out = h + bn(o2)
    k_out<<<TBSD_ / (EW * 4), EW>>>(out);
}